// round 1
// baseline (speedup 1.0000x reference)
#include <cuda_runtime.h>
#include <cuda_bf16.h>
#include <math.h>

// Problem constants (fixed-shape problem)
static constexpr int N_USER  = 100000;
static constexpr int N_ITEM  = 50000;
static constexpr int NN      = N_USER + N_ITEM;   // 150000
static constexpr int D       = 64;
static constexpr int E_EDGES = 2000000;
static constexpr int BATCH   = 8192;
static constexpr int ND      = NN * D;            // 9,600,000

// ---------------- device scratch (static globals, no allocation) -------------
__device__ float  g_deg_out[NN];
__device__ float  g_deg_in[NN];
__device__ float  g_norm[E_EDGES];
__device__ float  g_A_int[ND];
__device__ float  g_A_pop[ND];
__device__ float  g_B_int[ND];
__device__ float  g_B_pop[ND];
__device__ float  g_acc_int[ND];
__device__ float  g_acc_pop[ND];
__device__ double g_sums[4];
__device__ int    g_mask_is_u8;

// ---------------- helpers ----------------------------------------------------
__device__ __forceinline__ float softplus_f(float x) {
    // log1p(exp(x)), stable
    return fmaxf(x, 0.0f) + log1pf(expf(-fabsf(x)));
}
__device__ __forceinline__ float logsig_f(float x) {
    // log(sigmoid(x)) = min(x,0) - log1p(exp(-|x|))
    return fminf(x, 0.0f) - log1pf(expf(-fabsf(x)));
}

// ---------------- kernels ----------------------------------------------------
__global__ void k_zero_misc() {
    int i = blockIdx.x * blockDim.x + threadIdx.x;
    if (i < NN) { g_deg_out[i] = 0.0f; g_deg_in[i] = 0.0f; }
    if (i < 4)  g_sums[i] = 0.0;
    if (i == 0) g_mask_is_u8 = 0;
}

__global__ void k_degree(const int* __restrict__ es, const int* __restrict__ ed) {
    int i = blockIdx.x * blockDim.x + threadIdx.x;
    if (i >= E_EDGES) return;
    atomicAdd(&g_deg_out[es[i]], 1.0f);
    atomicAdd(&g_deg_in[ed[i]], 1.0f);
}

__global__ void k_norm(const int* __restrict__ es, const int* __restrict__ ed) {
    int i = blockIdx.x * blockDim.x + threadIdx.x;
    if (i >= E_EDGES) return;
    float a = rsqrtf(fmaxf(g_deg_out[es[i]], 1.0f));
    float c = rsqrtf(fmaxf(g_deg_in[ed[i]], 1.0f));
    g_norm[i] = a * c;
}

// Detect whether the mask buffer is byte-bool (any nonzero byte at pos%4!=0)
// or int32 0/1 (those positions are always zero on little-endian).
__global__ void k_maskdetect(const unsigned char* __restrict__ m) {
    int i = blockIdx.x * blockDim.x + threadIdx.x;
    int bad = 0;
    for (int j = i; j < BATCH; j += gridDim.x * blockDim.x)
        if ((j & 3) && m[j]) bad = 1;
    if (bad) g_mask_is_u8 = 1;
}

// selector: 0 -> (A_int, A_pop), 1 -> (B_int, B_pop)
__global__ void k_zero_pair(int sel) {
    int i = blockIdx.x * blockDim.x + threadIdx.x;
    if (i >= ND / 4) return;
    float4 z = make_float4(0.f, 0.f, 0.f, 0.f);
    float4* a = reinterpret_cast<float4*>(sel ? g_B_int : g_A_int);
    float4* b = reinterpret_cast<float4*>(sel ? g_B_pop : g_A_pop);
    a[i] = z;
    b[i] = z;
}

// Warp-per-edge scatter for BOTH embeddings.
// srcSel: 0 -> A, 1 -> B, 2 -> external (ei/ep).  dstSel: 0 -> A, 1 -> B.
__global__ void __launch_bounds__(256)
k_scatter(const float* __restrict__ ei, const float* __restrict__ ep,
          int srcSel, int dstSel,
          const int* __restrict__ es, const int* __restrict__ ed) {
    unsigned t = blockIdx.x * blockDim.x + threadIdx.x;
    unsigned e = t >> 5;
    unsigned lane = t & 31u;
    if (e >= (unsigned)E_EDGES) return;

    const float* si = (srcSel == 0) ? g_A_int : (srcSel == 1) ? g_B_int : ei;
    const float* sp = (srcSel == 0) ? g_A_pop : (srcSel == 1) ? g_B_pop : ep;
    float* di = dstSel ? g_B_int : g_A_int;
    float* dp = dstSel ? g_B_pop : g_A_pop;

    int s  = es[e];
    int d  = ed[e];
    float nm = g_norm[e];

    const float* srcRow = (lane < 16) ? (si + s * D) : (sp + s * D);
    float*       dstRow = (lane < 16) ? (di + d * D) : (dp + d * D);
    int c = (lane & 15) * 4;

    float4 v = *reinterpret_cast<const float4*>(srcRow + c);
    v.x *= nm; v.y *= nm; v.z *= nm; v.w *= nm;

    size_t gaddr = __cvta_generic_to_global(dstRow + c);
    asm volatile("red.global.add.v4.f32 [%0], {%1, %2, %3, %4};"
                 :: "l"(gaddr), "f"(v.x), "f"(v.y), "f"(v.z), "f"(v.w)
                 : "memory");
}

// acc = emb + A   (layer-0 + layer-1 outputs)
__global__ void k_acc_init(const float* __restrict__ ei, const float* __restrict__ ep) {
    int i = blockIdx.x * blockDim.x + threadIdx.x;
    if (i >= ND / 4) return;
    const float4* e4i = reinterpret_cast<const float4*>(ei);
    const float4* e4p = reinterpret_cast<const float4*>(ep);
    const float4* a4i = reinterpret_cast<const float4*>(g_A_int);
    const float4* a4p = reinterpret_cast<const float4*>(g_A_pop);
    float4* o4i = reinterpret_cast<float4*>(g_acc_int);
    float4* o4p = reinterpret_cast<float4*>(g_acc_pop);
    float4 x = e4i[i], y = a4i[i];
    o4i[i] = make_float4(x.x + y.x, x.y + y.y, x.z + y.z, x.w + y.w);
    x = e4p[i]; y = a4p[i];
    o4p[i] = make_float4(x.x + y.x, x.y + y.y, x.z + y.z, x.w + y.w);
}

// acc += buf(sel)
__global__ void k_acc_add(int sel) {
    int i = blockIdx.x * blockDim.x + threadIdx.x;
    if (i >= ND / 4) return;
    const float4* b4i = reinterpret_cast<const float4*>(sel ? g_B_int : g_A_int);
    const float4* b4p = reinterpret_cast<const float4*>(sel ? g_B_pop : g_A_pop);
    float4* o4i = reinterpret_cast<float4*>(g_acc_int);
    float4* o4p = reinterpret_cast<float4*>(g_acc_pop);
    float4 x = o4i[i], y = b4i[i];
    o4i[i] = make_float4(x.x + y.x, x.y + y.y, x.z + y.z, x.w + y.w);
    x = o4p[i]; y = b4p[i];
    o4p[i] = make_float4(x.x + y.x, x.y + y.y, x.z + y.z, x.w + y.w);
}

// One warp per triple. acc holds 4*f, so each dot is scaled by 1/16.
__global__ void __launch_bounds__(256)
k_score(const float* __restrict__ q, const float* __restrict__ bq,
        const int* __restrict__ user, const int* __restrict__ itp,
        const int* __restrict__ itn, const void* __restrict__ mask) {
    int t = blockIdx.x * blockDim.x + threadIdx.x;
    int w = t >> 5;
    int lane = t & 31;
    int wib = (threadIdx.x >> 5);       // warp in block (0..7)
    __shared__ float sred[8][4];

    float s0 = 0.f, s1 = 0.f, s2 = 0.f, s3 = 0.f;
    if (w < BATCH) {
        int u  = user[w];
        int p  = itp[w];
        int n  = itn[w];
        const float2* ui = reinterpret_cast<const float2*>(g_acc_int + (size_t)u * D);
        const float2* up = reinterpret_cast<const float2*>(g_acc_pop + (size_t)u * D);
        const float2* pi = reinterpret_cast<const float2*>(g_acc_int + (size_t)(p + N_USER) * D);
        const float2* pp = reinterpret_cast<const float2*>(g_acc_pop + (size_t)(p + N_USER) * D);
        const float2* ni = reinterpret_cast<const float2*>(g_acc_int + (size_t)(n + N_USER) * D);
        const float2* np = reinterpret_cast<const float2*>(g_acc_pop + (size_t)(n + N_USER) * D);

        float2 a = ui[lane], b2 = up[lane];
        float2 cp = pi[lane], dp = pp[lane];
        float2 cn = ni[lane], dn = np[lane];

        float pint = a.x * cp.x + a.y * cp.y;
        float nint = a.x * cn.x + a.y * cn.y;
        float ppop = b2.x * dp.x + b2.y * dp.y;
        float npop = b2.x * dn.x + b2.y * dn.y;

        #pragma unroll
        for (int o = 16; o > 0; o >>= 1) {
            pint += __shfl_xor_sync(0xffffffffu, pint, o);
            nint += __shfl_xor_sync(0xffffffffu, nint, o);
            ppop += __shfl_xor_sync(0xffffffffu, ppop, o);
            npop += __shfl_xor_sync(0xffffffffu, npop, o);
        }

        if (lane == 0) {
            const float inv16 = 0.0625f;
            pint *= inv16; nint *= inv16; ppop *= inv16; npop *= inv16;

            bool m;
            if (g_mask_is_u8)
                m = ((const unsigned char*)mask)[w] != 0;
            else
                m = ((const int*)mask)[w] != 0;
            float mf = m ? 1.0f : 0.0f;
            float nmf = 1.0f - mf;

            s0 = mf  * logsig_f(pint - nint);
            s1 = mf  * logsig_f(npop - ppop);
            s2 = nmf * logsig_f(ppop - npop);

            float popp = softplus_f(q[p]) + softplus_f(bq[p]);
            float popn = softplus_f(q[n]) + softplus_f(bq[n]);
            float ptot = pint + ppop;
            float ntot = nint + npop;
            s3 = logsig_f(tanhf(popp) * ptot - tanhf(popn) * ntot);
        }
    }
    if (lane == 0) {
        sred[wib][0] = s0; sred[wib][1] = s1; sred[wib][2] = s2; sred[wib][3] = s3;
    }
    __syncthreads();
    if (threadIdx.x < 4) {
        float tsum = 0.f;
        #pragma unroll
        for (int k = 0; k < 8; k++) tsum += sred[k][threadIdx.x];
        atomicAdd(&g_sums[threadIdx.x], (double)tsum);
    }
}

__global__ void k_final(float* __restrict__ out) {
    double invB = 1.0 / (double)BATCH;
    double s0 = g_sums[0], s1 = g_sums[1], s2 = g_sums[2], s3 = g_sums[3];
    double loss_int  = -s0 * invB;
    double loss_pop  = (-s1 + s2) * invB;
    double loss_tide = -s3 * invB;
    out[0] = (float)(0.1 * loss_int + 0.1 * loss_pop + 0.2 * loss_tide);
}

// ---------------- launch ------------------------------------------------------
extern "C" void kernel_launch(void* const* d_in, const int* in_sizes, int n_in,
                              void* d_out, int out_size) {
    const float* emb_int = (const float*)d_in[0];
    const float* emb_pop = (const float*)d_in[1];
    const float* q       = (const float*)d_in[2];
    const float* bq      = (const float*)d_in[3];
    const int*   user    = (const int*)d_in[4];
    const int*   itp     = (const int*)d_in[5];
    const int*   itn     = (const int*)d_in[6];
    const void*  mask    = d_in[7];
    const int*   es      = (const int*)d_in[8];
    const int*   ed      = (const int*)d_in[9];
    float* out = (float*)d_out;

    const int TB = 256;
    int gridE   = (E_EDGES + TB - 1) / TB;
    int gridN   = (NN + TB - 1) / TB;
    int gridND4 = (ND / 4 + TB - 1) / TB;
    int gridSc  = (int)(((long long)E_EDGES * 32 + TB - 1) / TB);
    int gridS   = (BATCH * 32 + TB - 1) / TB;

    k_zero_misc<<<gridN, TB>>>();
    k_degree<<<gridE, TB>>>(es, ed);
    k_norm<<<gridE, TB>>>(es, ed);
    k_maskdetect<<<8, TB>>>((const unsigned char*)mask);

    // layer 1: emb -> A ; acc = emb + A
    k_zero_pair<<<gridND4, TB>>>(0);
    k_scatter<<<gridSc, TB>>>(emb_int, emb_pop, /*src*/2, /*dst*/0, es, ed);
    k_acc_init<<<gridND4, TB>>>(emb_int, emb_pop);

    // layer 2: A -> B ; acc += B
    k_zero_pair<<<gridND4, TB>>>(1);
    k_scatter<<<gridSc, TB>>>(emb_int, emb_pop, /*src*/0, /*dst*/1, es, ed);
    k_acc_add<<<gridND4, TB>>>(1);

    // layer 3: B -> A ; acc += A
    k_zero_pair<<<gridND4, TB>>>(0);
    k_scatter<<<gridSc, TB>>>(emb_int, emb_pop, /*src*/1, /*dst*/0, es, ed);
    k_acc_add<<<gridND4, TB>>>(0);

    k_score<<<gridS, TB>>>(q, bq, user, itp, itn, mask);
    k_final<<<1, 1>>>(out);
}

// round 2
// speedup vs baseline: 2.4421x; 2.4421x over previous
#include <cuda_runtime.h>
#include <cuda_bf16.h>
#include <math.h>

// Problem constants (fixed-shape problem)
static constexpr int N_USER  = 100000;
static constexpr int N_ITEM  = 50000;
static constexpr int NN      = N_USER + N_ITEM;   // 150000
static constexpr int D       = 64;
static constexpr int E_EDGES = 2000000;
static constexpr int BATCH   = 8192;
static constexpr int ND      = NN * D;            // 9,600,000

static constexpr int SCAN_CHUNK = 1024;
static constexpr int NB_SCAN = (NN + SCAN_CHUNK - 1) / SCAN_CHUNK;  // 147

// ---------------- device scratch (static globals, no allocation) -------------
__device__ int    g_dego[NN];        // out-degree (int)
__device__ int    g_degi[NN];        // in-degree (int)
__device__ float  g_rdo[NN];         // rsqrt(max(deg_out,1))
__device__ float  g_rdi[NN];         // rsqrt(max(deg_in,1))
__device__ int    g_rowptr[NN];      // CSR start offsets (by dst)
__device__ int    g_cursor[NN];      // placement cursors
__device__ int    g_bsum[NB_SCAN];   // scan block sums
__device__ int    g_boff[NB_SCAN];   // scan block offsets
__device__ int    g_csr_src[E_EDGES];
__device__ float  g_csr_norm[E_EDGES];
__device__ float  g_A_int[ND];
__device__ float  g_A_pop[ND];
__device__ float  g_B_int[ND];
__device__ float  g_B_pop[ND];
__device__ float  g_C_int[ND];
__device__ float  g_C_pop[ND];
__device__ double g_sums[4];
__device__ int    g_mask_is_u8;

// ---------------- helpers ----------------------------------------------------
__device__ __forceinline__ float softplus_f(float x) {
    return fmaxf(x, 0.0f) + log1pf(expf(-fabsf(x)));
}
__device__ __forceinline__ float logsig_f(float x) {
    return fminf(x, 0.0f) - log1pf(expf(-fabsf(x)));
}

// ---------------- kernels ----------------------------------------------------
__global__ void k_init() {
    int i = blockIdx.x * blockDim.x + threadIdx.x;
    if (i < NN) { g_dego[i] = 0; g_degi[i] = 0; }
    if (i < 4)  g_sums[i] = 0.0;
    if (i == 0) g_mask_is_u8 = 0;
}

__global__ void k_degree(const int* __restrict__ es, const int* __restrict__ ed) {
    int i = blockIdx.x * blockDim.x + threadIdx.x;
    if (i >= E_EDGES) return;
    atomicAdd(&g_dego[es[i]], 1);
    atomicAdd(&g_degi[ed[i]], 1);
}

__global__ void k_rsqrt() {
    int i = blockIdx.x * blockDim.x + threadIdx.x;
    if (i >= NN) return;
    g_rdo[i] = rsqrtf(fmaxf((float)g_dego[i], 1.0f));
    g_rdi[i] = rsqrtf(fmaxf((float)g_degi[i], 1.0f));
}

// ---- 3-phase exclusive scan of g_degi -> g_rowptr ----
__global__ void k_scan_a() {
    __shared__ int sdata[256];
    int base = blockIdx.x * SCAN_CHUNK;
    int t = threadIdx.x;
    int s = 0;
    #pragma unroll
    for (int j = 0; j < 4; j++) {
        int idx = base + t * 4 + j;
        if (idx < NN) s += g_degi[idx];
    }
    sdata[t] = s;
    __syncthreads();
    for (int off = 128; off > 0; off >>= 1) {
        if (t < off) sdata[t] += sdata[t + off];
        __syncthreads();
    }
    if (t == 0) g_bsum[blockIdx.x] = sdata[0];
}

__global__ void k_scan_b() {
    if (threadIdx.x == 0) {
        int run = 0;
        for (int b = 0; b < NB_SCAN; b++) {
            g_boff[b] = run;
            run += g_bsum[b];
        }
    }
}

__global__ void k_scan_c() {
    __shared__ int sdata[256];
    int base = blockIdx.x * SCAN_CHUNK;
    int t = threadIdx.x;
    int v[4];
    int tsum = 0;
    #pragma unroll
    for (int j = 0; j < 4; j++) {
        int idx = base + t * 4 + j;
        v[j] = (idx < NN) ? g_degi[idx] : 0;
        tsum += v[j];
    }
    sdata[t] = tsum;
    __syncthreads();
    // Hillis-Steele inclusive scan
    for (int off = 1; off < 256; off <<= 1) {
        int tmp = (t >= off) ? sdata[t - off] : 0;
        __syncthreads();
        sdata[t] += tmp;
        __syncthreads();
    }
    int run = sdata[t] - tsum + g_boff[blockIdx.x];
    #pragma unroll
    for (int j = 0; j < 4; j++) {
        int idx = base + t * 4 + j;
        if (idx < NN) {
            g_rowptr[idx] = run;
            g_cursor[idx] = run;
            run += v[j];
        }
    }
}

__global__ void k_place(const int* __restrict__ es, const int* __restrict__ ed) {
    int i = blockIdx.x * blockDim.x + threadIdx.x;
    if (i >= E_EDGES) return;
    int s = es[i];
    int d = ed[i];
    int pos = atomicAdd(&g_cursor[d], 1);
    g_csr_src[pos] = s;
    g_csr_norm[pos] = g_rdo[s] * g_rdi[d];
}

// Detect whether the mask buffer is byte-bool or int32 0/1.
__global__ void k_maskdetect(const unsigned char* __restrict__ m) {
    int i = blockIdx.x * blockDim.x + threadIdx.x;
    int bad = 0;
    for (int j = i; j < BATCH; j += gridDim.x * blockDim.x)
        if ((j & 3) && m[j]) bad = 1;
    if (bad) g_mask_is_u8 = 1;
}

// CSR gather: one warp per destination node. lanes 0-15 int emb, 16-31 pop emb.
// srcSel: 2 -> external (ei/ep), 0 -> A, 1 -> B.  Writes into dst buffers.
__global__ void __launch_bounds__(256)
k_gather(const float* __restrict__ ei, const float* __restrict__ ep,
         int srcSel, float* __restrict__ di, float* __restrict__ dp) {
    unsigned t = blockIdx.x * blockDim.x + threadIdx.x;
    unsigned node = t >> 5;
    unsigned lane = t & 31u;
    if (node >= (unsigned)NN) return;

    const float* si = (srcSel == 0) ? g_A_int : (srcSel == 1) ? g_B_int : ei;
    const float* sp = (srcSel == 0) ? g_A_pop : (srcSel == 1) ? g_B_pop : ep;
    const float* srcBase = (lane < 16) ? si : sp;
    int c = (lane & 15) * 4;

    int start = g_rowptr[node];
    int cnt   = g_degi[node];

    float4 acc = make_float4(0.f, 0.f, 0.f, 0.f);
    for (int k0 = 0; k0 < cnt; k0 += 32) {
        int kk = k0 + (int)lane;
        int s = 0; float nm = 0.f;
        if (kk < cnt) {
            s  = g_csr_src[start + kk];
            nm = g_csr_norm[start + kk];
        }
        int lim = min(32, cnt - k0);
        for (int j = 0; j < lim; j++) {
            int   sj = __shfl_sync(0xffffffffu, s,  j);
            float nj = __shfl_sync(0xffffffffu, nm, j);
            float4 v = *reinterpret_cast<const float4*>(srcBase + (size_t)sj * D + c);
            acc.x += nj * v.x;
            acc.y += nj * v.y;
            acc.z += nj * v.z;
            acc.w += nj * v.w;
        }
    }
    float* dstBase = (lane < 16) ? di : dp;
    *reinterpret_cast<float4*>(dstBase + (size_t)node * D + c) = acc;
}

// One warp per triple; acc rows computed on the fly: e0 + A + B + C (= 4*f).
// Dots therefore scale by 1/16.
__global__ void __launch_bounds__(256)
k_score(const float* __restrict__ ei, const float* __restrict__ ep,
        const float* __restrict__ q, const float* __restrict__ bq,
        const int* __restrict__ user, const int* __restrict__ itp,
        const int* __restrict__ itn, const void* __restrict__ mask) {
    int t = blockIdx.x * blockDim.x + threadIdx.x;
    int w = t >> 5;
    int lane = t & 31;
    int wib = (threadIdx.x >> 5);
    __shared__ float sred[8][4];

    float s0 = 0.f, s1 = 0.f, s2 = 0.f, s3 = 0.f;
    if (w < BATCH) {
        int u  = user[w];
        int p  = itp[w];
        int n  = itn[w];
        size_t ru = (size_t)u * D;
        size_t rp = (size_t)(p + N_USER) * D;
        size_t rn = (size_t)(n + N_USER) * D;

        auto rowsum = [&](const float* e, const float* a, const float* b,
                          const float* cc, size_t r) -> float2 {
            const float2* e2 = reinterpret_cast<const float2*>(e + r);
            const float2* a2 = reinterpret_cast<const float2*>(a + r);
            const float2* b2 = reinterpret_cast<const float2*>(b + r);
            const float2* c2 = reinterpret_cast<const float2*>(cc + r);
            float2 x = e2[lane], y = a2[lane], z = b2[lane], v = c2[lane];
            return make_float2(x.x + y.x + z.x + v.x, x.y + y.y + z.y + v.y);
        };

        float2 a  = rowsum(ei, g_A_int, g_B_int, g_C_int, ru);
        float2 bb = rowsum(ep, g_A_pop, g_B_pop, g_C_pop, ru);
        float2 cp = rowsum(ei, g_A_int, g_B_int, g_C_int, rp);
        float2 dp = rowsum(ep, g_A_pop, g_B_pop, g_C_pop, rp);
        float2 cn = rowsum(ei, g_A_int, g_B_int, g_C_int, rn);
        float2 dn = rowsum(ep, g_A_pop, g_B_pop, g_C_pop, rn);

        float pint = a.x * cp.x + a.y * cp.y;
        float nint = a.x * cn.x + a.y * cn.y;
        float ppop = bb.x * dp.x + bb.y * dp.y;
        float npop = bb.x * dn.x + bb.y * dn.y;

        #pragma unroll
        for (int o = 16; o > 0; o >>= 1) {
            pint += __shfl_xor_sync(0xffffffffu, pint, o);
            nint += __shfl_xor_sync(0xffffffffu, nint, o);
            ppop += __shfl_xor_sync(0xffffffffu, ppop, o);
            npop += __shfl_xor_sync(0xffffffffu, npop, o);
        }

        if (lane == 0) {
            const float inv16 = 0.0625f;
            pint *= inv16; nint *= inv16; ppop *= inv16; npop *= inv16;

            bool m;
            if (g_mask_is_u8)
                m = ((const unsigned char*)mask)[w] != 0;
            else
                m = ((const int*)mask)[w] != 0;
            float mf = m ? 1.0f : 0.0f;
            float nmf = 1.0f - mf;

            s0 = mf  * logsig_f(pint - nint);
            s1 = mf  * logsig_f(npop - ppop);
            s2 = nmf * logsig_f(ppop - npop);

            float popp = softplus_f(q[p]) + softplus_f(bq[p]);
            float popn = softplus_f(q[n]) + softplus_f(bq[n]);
            float ptot = pint + ppop;
            float ntot = nint + npop;
            s3 = logsig_f(tanhf(popp) * ptot - tanhf(popn) * ntot);
        }
    }
    if (lane == 0) {
        sred[wib][0] = s0; sred[wib][1] = s1; sred[wib][2] = s2; sred[wib][3] = s3;
    }
    __syncthreads();
    if (threadIdx.x < 4) {
        float tsum = 0.f;
        #pragma unroll
        for (int k = 0; k < 8; k++) tsum += sred[k][threadIdx.x];
        atomicAdd(&g_sums[threadIdx.x], (double)tsum);
    }
}

__global__ void k_final(float* __restrict__ out) {
    double invB = 1.0 / (double)BATCH;
    double s0 = g_sums[0], s1 = g_sums[1], s2 = g_sums[2], s3 = g_sums[3];
    double loss_int  = -s0 * invB;
    double loss_pop  = (-s1 + s2) * invB;
    double loss_tide = -s3 * invB;
    out[0] = (float)(0.1 * loss_int + 0.1 * loss_pop + 0.2 * loss_tide);
}

// ---------------- launch ------------------------------------------------------
extern "C" void kernel_launch(void* const* d_in, const int* in_sizes, int n_in,
                              void* d_out, int out_size) {
    const float* emb_int = (const float*)d_in[0];
    const float* emb_pop = (const float*)d_in[1];
    const float* q       = (const float*)d_in[2];
    const float* bq      = (const float*)d_in[3];
    const int*   user    = (const int*)d_in[4];
    const int*   itp     = (const int*)d_in[5];
    const int*   itn     = (const int*)d_in[6];
    const void*  mask    = d_in[7];
    const int*   es      = (const int*)d_in[8];
    const int*   ed      = (const int*)d_in[9];
    float* out = (float*)d_out;

    const int TB = 256;
    int gridE  = (E_EDGES + TB - 1) / TB;
    int gridN  = (NN + TB - 1) / TB;
    int gridG  = (int)(((long long)NN * 32 + TB - 1) / TB);
    int gridS  = (BATCH * 32 + TB - 1) / TB;

    // Resolve device-symbol addresses for layer buffers (host API, no alloc).
    float *A_int, *A_pop, *B_int, *B_pop, *C_int, *C_pop;
    cudaGetSymbolAddress((void**)&A_int, g_A_int);
    cudaGetSymbolAddress((void**)&A_pop, g_A_pop);
    cudaGetSymbolAddress((void**)&B_int, g_B_int);
    cudaGetSymbolAddress((void**)&B_pop, g_B_pop);
    cudaGetSymbolAddress((void**)&C_int, g_C_int);
    cudaGetSymbolAddress((void**)&C_pop, g_C_pop);

    k_init<<<gridN, TB>>>();
    k_degree<<<gridE, TB>>>(es, ed);
    k_rsqrt<<<gridN, TB>>>();
    k_scan_a<<<NB_SCAN, 256>>>();
    k_scan_b<<<1, 32>>>();
    k_scan_c<<<NB_SCAN, 256>>>();
    k_place<<<gridE, TB>>>(es, ed);
    k_maskdetect<<<8, TB>>>((const unsigned char*)mask);

    // layer 1: emb -> A
    k_gather<<<gridG, TB>>>(emb_int, emb_pop, /*src*/2, A_int, A_pop);
    // layer 2: A -> B
    k_gather<<<gridG, TB>>>(emb_int, emb_pop, /*src*/0, B_int, B_pop);
    // layer 3: B -> C
    k_gather<<<gridG, TB>>>(emb_int, emb_pop, /*src*/1, C_int, C_pop);

    k_score<<<gridS, TB>>>(emb_int, emb_pop, q, bq, user, itp, itn, mask);
    k_final<<<1, 1>>>(out);
}

// round 3
// speedup vs baseline: 3.2039x; 1.3119x over previous
#include <cuda_runtime.h>
#include <cuda_fp16.h>
#include <math.h>

// Problem constants (fixed-shape problem)
static constexpr int N_USER  = 100000;
static constexpr int N_ITEM  = 50000;
static constexpr int NN      = N_USER + N_ITEM;   // 150000
static constexpr int D       = 64;
static constexpr int E_EDGES = 2000000;
static constexpr int BATCH   = 8192;
static constexpr int ND      = NN * D;            // 9,600,000

static constexpr int SCAN_CHUNK = 1024;
static constexpr int NB_SCAN = (NN + SCAN_CHUNK - 1) / SCAN_CHUNK;  // 147

// ---------------- device scratch (static globals, no allocation) -------------
__device__ int    g_dego[NN];
__device__ int    g_degi[NN];
__device__ int    g_rowptr[NN];
__device__ int    g_cursor[NN];
__device__ int    g_bsum[NB_SCAN];
__device__ int    g_csr_src[E_EDGES];
__device__ float  g_csr_norm[E_EDGES];
__device__ __half g_E_int[ND];   // fp16 copy of emb_int
__device__ __half g_E_pop[ND];   // fp16 copy of emb_pop
__device__ __half g_A_int[ND];
__device__ __half g_A_pop[ND];
__device__ __half g_B_int[ND];
__device__ __half g_B_pop[ND];
__device__ __half g_C_int[ND];
__device__ __half g_C_pop[ND];
__device__ double g_sums[4];
__device__ int    g_mask_is_u8;

// ---------------- helpers ----------------------------------------------------
__device__ __forceinline__ float softplus_f(float x) {
    return fmaxf(x, 0.0f) + log1pf(expf(-fabsf(x)));
}
__device__ __forceinline__ float logsig_f(float x) {
    return fminf(x, 0.0f) - log1pf(expf(-fabsf(x)));
}

// ---------------- kernels ----------------------------------------------------
// Fused: fp32->fp16 conversion of both embeddings + zero degrees + zero sums.
__global__ void k_init_convert(const float* __restrict__ ei, const float* __restrict__ ep) {
    int i = blockIdx.x * blockDim.x + threadIdx.x;
    if (i < ND / 2) {
        float2 v = reinterpret_cast<const float2*>(ei)[i];
        reinterpret_cast<__half2*>(g_E_int)[i] = __floats2half2_rn(v.x, v.y);
        v = reinterpret_cast<const float2*>(ep)[i];
        reinterpret_cast<__half2*>(g_E_pop)[i] = __floats2half2_rn(v.x, v.y);
    }
    if (i < NN) { g_dego[i] = 0; g_degi[i] = 0; }
    if (i < 4)  g_sums[i] = 0.0;
    if (i == 0) g_mask_is_u8 = 0;
}

// Degree counting + mask-layout detection (first BATCH threads).
__global__ void k_degree(const int* __restrict__ es, const int* __restrict__ ed,
                         const unsigned char* __restrict__ m) {
    int i = blockIdx.x * blockDim.x + threadIdx.x;
    if (i < BATCH) {
        if ((i & 3) && m[i]) atomicOr(&g_mask_is_u8, 1);
    }
    if (i >= E_EDGES) return;
    atomicAdd(&g_dego[es[i]], 1);
    atomicAdd(&g_degi[ed[i]], 1);
}

// Per-chunk sums of g_degi.
__global__ void k_scan_a() {
    __shared__ int sdata[256];
    int base = blockIdx.x * SCAN_CHUNK;
    int t = threadIdx.x;
    int s = 0;
    #pragma unroll
    for (int j = 0; j < 4; j++) {
        int idx = base + t * 4 + j;
        if (idx < NN) s += g_degi[idx];
    }
    sdata[t] = s;
    __syncthreads();
    for (int off = 128; off > 0; off >>= 1) {
        if (t < off) sdata[t] += sdata[t + off];
        __syncthreads();
    }
    if (t == 0) g_bsum[blockIdx.x] = sdata[0];
}

// Fused: each block redundantly scans block sums, then writes its rowptr range.
__global__ void k_scan_bc() {
    __shared__ int sb[256];
    __shared__ int sdata[256];
    int t = threadIdx.x;

    sb[t] = (t < NB_SCAN) ? g_bsum[t] : 0;
    __syncthreads();
    // inclusive scan over sb
    for (int off = 1; off < 256; off <<= 1) {
        int tmp = (t >= off) ? sb[t - off] : 0;
        __syncthreads();
        sb[t] += tmp;
        __syncthreads();
    }
    int boff = (blockIdx.x == 0) ? 0 : sb[blockIdx.x - 1];

    int base = blockIdx.x * SCAN_CHUNK;
    int v[4];
    int tsum = 0;
    #pragma unroll
    for (int j = 0; j < 4; j++) {
        int idx = base + t * 4 + j;
        v[j] = (idx < NN) ? g_degi[idx] : 0;
        tsum += v[j];
    }
    sdata[t] = tsum;
    __syncthreads();
    for (int off = 1; off < 256; off <<= 1) {
        int tmp = (t >= off) ? sdata[t - off] : 0;
        __syncthreads();
        sdata[t] += tmp;
        __syncthreads();
    }
    int run = sdata[t] - tsum + boff;
    #pragma unroll
    for (int j = 0; j < 4; j++) {
        int idx = base + t * 4 + j;
        if (idx < NN) {
            g_rowptr[idx] = run;
            g_cursor[idx] = run;
            run += v[j];
        }
    }
}

// Edge placement; norm computed from degrees on the fly.
__global__ void k_place(const int* __restrict__ es, const int* __restrict__ ed) {
    int i = blockIdx.x * blockDim.x + threadIdx.x;
    if (i >= E_EDGES) return;
    int s = es[i];
    int d = ed[i];
    int pos = atomicAdd(&g_cursor[d], 1);
    g_csr_src[pos] = s;
    g_csr_norm[pos] = rsqrtf(fmaxf((float)g_dego[s], 1.0f))
                    * rsqrtf(fmaxf((float)g_degi[d], 1.0f));
}

// CSR gather: one warp per destination node. lanes 0-15 int, 16-31 pop.
// fp16 sources, fp32 accumulate, fp16 store.
__global__ void __launch_bounds__(256)
k_gather(const __half* __restrict__ si, const __half* __restrict__ sp,
         __half* __restrict__ di, __half* __restrict__ dp) {
    unsigned t = blockIdx.x * blockDim.x + threadIdx.x;
    unsigned node = t >> 5;
    unsigned lane = t & 31u;
    if (node >= (unsigned)NN) return;

    const __half* srcBase = (lane < 16) ? si : sp;
    int c = (lane & 15) * 4;  // half index within row

    int start = g_rowptr[node];
    int cnt   = g_degi[node];

    float4 acc = make_float4(0.f, 0.f, 0.f, 0.f);
    for (int k0 = 0; k0 < cnt; k0 += 32) {
        int kk = k0 + (int)lane;
        int s = 0; float nm = 0.f;
        if (kk < cnt) {
            s  = g_csr_src[start + kk];
            nm = g_csr_norm[start + kk];
        }
        int lim = min(32, cnt - k0);
        for (int j = 0; j < lim; j++) {
            int   sj = __shfl_sync(0xffffffffu, s,  j);
            float nj = __shfl_sync(0xffffffffu, nm, j);
            uint2 raw = *reinterpret_cast<const uint2*>(srcBase + (size_t)sj * D + c);
            __half2 h0 = *reinterpret_cast<__half2*>(&raw.x);
            __half2 h1 = *reinterpret_cast<__half2*>(&raw.y);
            float2 f0 = __half22float2(h0);
            float2 f1 = __half22float2(h1);
            acc.x += nj * f0.x;
            acc.y += nj * f0.y;
            acc.z += nj * f1.x;
            acc.w += nj * f1.y;
        }
    }
    __half* dstBase = (lane < 16) ? di : dp;
    __half2 o0 = __floats2half2_rn(acc.x, acc.y);
    __half2 o1 = __floats2half2_rn(acc.z, acc.w);
    uint2 outw;
    outw.x = *reinterpret_cast<unsigned*>(&o0);
    outw.y = *reinterpret_cast<unsigned*>(&o1);
    *reinterpret_cast<uint2*>(dstBase + (size_t)node * D + c) = outw;
}

// One warp per triple; acc rows computed on the fly: e0(fp32) + A + B + C (fp16).
// acc = 4 * mean, so dots scale by 1/16.
__global__ void __launch_bounds__(256)
k_score(const float* __restrict__ ei, const float* __restrict__ ep,
        const float* __restrict__ q, const float* __restrict__ bq,
        const int* __restrict__ user, const int* __restrict__ itp,
        const int* __restrict__ itn, const void* __restrict__ mask) {
    int t = blockIdx.x * blockDim.x + threadIdx.x;
    int w = t >> 5;
    int lane = t & 31;
    int wib = (threadIdx.x >> 5);
    __shared__ float sred[8][4];

    float s0 = 0.f, s1 = 0.f, s2 = 0.f, s3 = 0.f;
    if (w < BATCH) {
        int u  = user[w];
        int p  = itp[w];
        int n  = itn[w];
        size_t ru = (size_t)u * D;
        size_t rp = (size_t)(p + N_USER) * D;
        size_t rn = (size_t)(n + N_USER) * D;

        auto rowsum = [&](const float* e, const __half* a, const __half* b,
                          const __half* cc, size_t r) -> float2 {
            float2 x = reinterpret_cast<const float2*>(e + r)[lane];
            float2 fa = __half22float2(reinterpret_cast<const __half2*>(a + r)[lane]);
            float2 fb = __half22float2(reinterpret_cast<const __half2*>(b + r)[lane]);
            float2 fc = __half22float2(reinterpret_cast<const __half2*>(cc + r)[lane]);
            return make_float2(x.x + fa.x + fb.x + fc.x, x.y + fa.y + fb.y + fc.y);
        };

        float2 a  = rowsum(ei, g_A_int, g_B_int, g_C_int, ru);
        float2 bb = rowsum(ep, g_A_pop, g_B_pop, g_C_pop, ru);
        float2 cp = rowsum(ei, g_A_int, g_B_int, g_C_int, rp);
        float2 dp = rowsum(ep, g_A_pop, g_B_pop, g_C_pop, rp);
        float2 cn = rowsum(ei, g_A_int, g_B_int, g_C_int, rn);
        float2 dn = rowsum(ep, g_A_pop, g_B_pop, g_C_pop, rn);

        float pint = a.x * cp.x + a.y * cp.y;
        float nint = a.x * cn.x + a.y * cn.y;
        float ppop = bb.x * dp.x + bb.y * dp.y;
        float npop = bb.x * dn.x + bb.y * dn.y;

        #pragma unroll
        for (int o = 16; o > 0; o >>= 1) {
            pint += __shfl_xor_sync(0xffffffffu, pint, o);
            nint += __shfl_xor_sync(0xffffffffu, nint, o);
            ppop += __shfl_xor_sync(0xffffffffu, ppop, o);
            npop += __shfl_xor_sync(0xffffffffu, npop, o);
        }

        if (lane == 0) {
            const float inv16 = 0.0625f;
            pint *= inv16; nint *= inv16; ppop *= inv16; npop *= inv16;

            bool m;
            if (g_mask_is_u8)
                m = ((const unsigned char*)mask)[w] != 0;
            else
                m = ((const int*)mask)[w] != 0;
            float mf = m ? 1.0f : 0.0f;
            float nmf = 1.0f - mf;

            s0 = mf  * logsig_f(pint - nint);
            s1 = mf  * logsig_f(npop - ppop);
            s2 = nmf * logsig_f(ppop - npop);

            float popp = softplus_f(q[p]) + softplus_f(bq[p]);
            float popn = softplus_f(q[n]) + softplus_f(bq[n]);
            float ptot = pint + ppop;
            float ntot = nint + npop;
            s3 = logsig_f(tanhf(popp) * ptot - tanhf(popn) * ntot);
        }
    }
    if (lane == 0) {
        sred[wib][0] = s0; sred[wib][1] = s1; sred[wib][2] = s2; sred[wib][3] = s3;
    }
    __syncthreads();
    if (threadIdx.x < 4) {
        float tsum = 0.f;
        #pragma unroll
        for (int k = 0; k < 8; k++) tsum += sred[k][threadIdx.x];
        atomicAdd(&g_sums[threadIdx.x], (double)tsum);
    }
}

__global__ void k_final(float* __restrict__ out) {
    double invB = 1.0 / (double)BATCH;
    double s0 = g_sums[0], s1 = g_sums[1], s2 = g_sums[2], s3 = g_sums[3];
    double loss_int  = -s0 * invB;
    double loss_pop  = (-s1 + s2) * invB;
    double loss_tide = -s3 * invB;
    out[0] = (float)(0.1 * loss_int + 0.1 * loss_pop + 0.2 * loss_tide);
}

// ---------------- launch ------------------------------------------------------
extern "C" void kernel_launch(void* const* d_in, const int* in_sizes, int n_in,
                              void* d_out, int out_size) {
    const float* emb_int = (const float*)d_in[0];
    const float* emb_pop = (const float*)d_in[1];
    const float* q       = (const float*)d_in[2];
    const float* bq      = (const float*)d_in[3];
    const int*   user    = (const int*)d_in[4];
    const int*   itp     = (const int*)d_in[5];
    const int*   itn     = (const int*)d_in[6];
    const void*  mask    = d_in[7];
    const int*   es      = (const int*)d_in[8];
    const int*   ed      = (const int*)d_in[9];
    float* out = (float*)d_out;

    const int TB = 256;
    int gridE  = (E_EDGES + TB - 1) / TB;
    int gridC  = (ND / 2 + TB - 1) / TB;
    int gridG  = (int)(((long long)NN * 32 + TB - 1) / TB);
    int gridS  = (BATCH * 32 + TB - 1) / TB;

    __half *E_int, *E_pop, *A_int, *A_pop, *B_int, *B_pop, *C_int, *C_pop;
    cudaGetSymbolAddress((void**)&E_int, g_E_int);
    cudaGetSymbolAddress((void**)&E_pop, g_E_pop);
    cudaGetSymbolAddress((void**)&A_int, g_A_int);
    cudaGetSymbolAddress((void**)&A_pop, g_A_pop);
    cudaGetSymbolAddress((void**)&B_int, g_B_int);
    cudaGetSymbolAddress((void**)&B_pop, g_B_pop);
    cudaGetSymbolAddress((void**)&C_int, g_C_int);
    cudaGetSymbolAddress((void**)&C_pop, g_C_pop);

    k_init_convert<<<gridC, TB>>>(emb_int, emb_pop);
    k_degree<<<gridE, TB>>>(es, ed, (const unsigned char*)mask);
    k_scan_a<<<NB_SCAN, 256>>>();
    k_scan_bc<<<NB_SCAN, 256>>>();
    k_place<<<gridE, TB>>>(es, ed);

    k_gather<<<gridG, TB>>>(E_int, E_pop, A_int, A_pop);   // layer 1
    k_gather<<<gridG, TB>>>(A_int, A_pop, B_int, B_pop);   // layer 2
    k_gather<<<gridG, TB>>>(B_int, B_pop, C_int, C_pop);   // layer 3

    k_score<<<gridS, TB>>>(emb_int, emb_pop, q, bq, user, itp, itn, mask);
    k_final<<<1, 1>>>(out);
}

// round 4
// speedup vs baseline: 3.3957x; 1.0598x over previous
#include <cuda_runtime.h>
#include <cuda_fp16.h>
#include <math.h>

// Problem constants (fixed-shape problem)
static constexpr int N_USER  = 100000;
static constexpr int N_ITEM  = 50000;
static constexpr int NN      = N_USER + N_ITEM;   // 150000
static constexpr int D       = 64;
static constexpr int E_EDGES = 2000000;
static constexpr int BATCH   = 8192;
static constexpr int ND      = NN * D;            // 9,600,000

static constexpr int SCAN_CHUNK = 1024;
static constexpr int NB_SCAN = (NN + SCAN_CHUNK - 1) / SCAN_CHUNK;  // 147

// ---------------- device scratch (static globals, no allocation) -------------
__device__ int    g_dego[NN];
__device__ int    g_degi[NN];
__device__ int    g_rowptr[NN];
__device__ int    g_cursor[NN];
__device__ int    g_bsum[NB_SCAN];
__device__ int2   g_csr[E_EDGES];          // .x = src node, .y = norm (float bits)
__device__ unsigned char g_need[NN];       // layer-3 pruning flags
__device__ __half g_E_int[ND];
__device__ __half g_E_pop[ND];
__device__ __half g_A_int[ND];
__device__ __half g_A_pop[ND];
__device__ __half g_B_int[ND];
__device__ __half g_B_pop[ND];
__device__ __half g_C_int[ND];
__device__ __half g_C_pop[ND];
__device__ double g_sums[4];
__device__ int    g_mask_is_u8;

// ---------------- helpers ----------------------------------------------------
__device__ __forceinline__ float softplus_f(float x) {
    return fmaxf(x, 0.0f) + log1pf(expf(-fabsf(x)));
}
__device__ __forceinline__ float logsig_f(float x) {
    return fminf(x, 0.0f) - log1pf(expf(-fabsf(x)));
}
__device__ __forceinline__ void fma_edge(float4& acc, float n, uint2 raw) {
    __half2 h0 = *reinterpret_cast<__half2*>(&raw.x);
    __half2 h1 = *reinterpret_cast<__half2*>(&raw.y);
    float2 f0 = __half22float2(h0);
    float2 f1 = __half22float2(h1);
    acc.x += n * f0.x;
    acc.y += n * f0.y;
    acc.z += n * f1.x;
    acc.w += n * f1.y;
}

// ---------------- kernels ----------------------------------------------------
// Fused: fp32->fp16 conversion + zero degrees/flags/sums.
__global__ void k_init_convert(const float* __restrict__ ei, const float* __restrict__ ep) {
    int i = blockIdx.x * blockDim.x + threadIdx.x;
    if (i < ND / 2) {
        float2 v = reinterpret_cast<const float2*>(ei)[i];
        reinterpret_cast<__half2*>(g_E_int)[i] = __floats2half2_rn(v.x, v.y);
        v = reinterpret_cast<const float2*>(ep)[i];
        reinterpret_cast<__half2*>(g_E_pop)[i] = __floats2half2_rn(v.x, v.y);
    }
    if (i < NN) { g_dego[i] = 0; g_degi[i] = 0; g_need[i] = 0; }
    if (i < 4)  g_sums[i] = 0.0;
    if (i == 0) g_mask_is_u8 = 0;
}

// Degree counting + mask-layout detect + layer-3 need flags.
__global__ void k_degree(const int* __restrict__ es, const int* __restrict__ ed,
                         const unsigned char* __restrict__ m,
                         const int* __restrict__ user, const int* __restrict__ itp,
                         const int* __restrict__ itn) {
    int i = blockIdx.x * blockDim.x + threadIdx.x;
    if (i < BATCH) {
        if ((i & 3) && m[i]) atomicOr(&g_mask_is_u8, 1);
        g_need[user[i]] = 1;
        g_need[itp[i] + N_USER] = 1;
        g_need[itn[i] + N_USER] = 1;
    }
    if (i >= E_EDGES) return;
    atomicAdd(&g_dego[es[i]], 1);
    atomicAdd(&g_degi[ed[i]], 1);
}

// Per-chunk sums of g_degi.
__global__ void k_scan_a() {
    __shared__ int sdata[256];
    int base = blockIdx.x * SCAN_CHUNK;
    int t = threadIdx.x;
    int s = 0;
    #pragma unroll
    for (int j = 0; j < 4; j++) {
        int idx = base + t * 4 + j;
        if (idx < NN) s += g_degi[idx];
    }
    sdata[t] = s;
    __syncthreads();
    for (int off = 128; off > 0; off >>= 1) {
        if (t < off) sdata[t] += sdata[t + off];
        __syncthreads();
    }
    if (t == 0) g_bsum[blockIdx.x] = sdata[0];
}

// Fused: each block redundantly scans block sums, then writes its rowptr range.
__global__ void k_scan_bc() {
    __shared__ int sb[256];
    __shared__ int sdata[256];
    int t = threadIdx.x;

    sb[t] = (t < NB_SCAN) ? g_bsum[t] : 0;
    __syncthreads();
    for (int off = 1; off < 256; off <<= 1) {
        int tmp = (t >= off) ? sb[t - off] : 0;
        __syncthreads();
        sb[t] += tmp;
        __syncthreads();
    }
    int boff = (blockIdx.x == 0) ? 0 : sb[blockIdx.x - 1];

    int base = blockIdx.x * SCAN_CHUNK;
    int v[4];
    int tsum = 0;
    #pragma unroll
    for (int j = 0; j < 4; j++) {
        int idx = base + t * 4 + j;
        v[j] = (idx < NN) ? g_degi[idx] : 0;
        tsum += v[j];
    }
    sdata[t] = tsum;
    __syncthreads();
    for (int off = 1; off < 256; off <<= 1) {
        int tmp = (t >= off) ? sdata[t - off] : 0;
        __syncthreads();
        sdata[t] += tmp;
        __syncthreads();
    }
    int run = sdata[t] - tsum + boff;
    #pragma unroll
    for (int j = 0; j < 4; j++) {
        int idx = base + t * 4 + j;
        if (idx < NN) {
            g_rowptr[idx] = run;
            g_cursor[idx] = run;
            run += v[j];
        }
    }
}

// Edge placement; norm computed from degrees; packed (src, norm) write.
__global__ void k_place(const int* __restrict__ es, const int* __restrict__ ed) {
    int i = blockIdx.x * blockDim.x + threadIdx.x;
    if (i >= E_EDGES) return;
    int s = es[i];
    int d = ed[i];
    int pos = atomicAdd(&g_cursor[d], 1);
    float nm = rsqrtf(fmaxf((float)g_dego[s], 1.0f))
             * rsqrtf(fmaxf((float)g_degi[d], 1.0f));
    g_csr[pos] = make_int2(s, __float_as_int(nm));
}

// CSR gather: one warp per destination node. lanes 0-15 int, 16-31 pop.
// fp16 sources, fp32 accumulate, fp16 store. 4-wide MLP unroll.
// prune != 0: only compute nodes flagged in g_need.
__global__ void __launch_bounds__(256)
k_gather(const __half* __restrict__ si, const __half* __restrict__ sp,
         __half* __restrict__ di, __half* __restrict__ dp, int prune) {
    unsigned t = blockIdx.x * blockDim.x + threadIdx.x;
    unsigned node = t >> 5;
    unsigned lane = t & 31u;
    if (node >= (unsigned)NN) return;
    if (prune && !g_need[node]) return;

    const __half* srcBase = (lane < 16) ? si : sp;
    int c = (lane & 15) * 4;  // half index within row

    int start = g_rowptr[node];
    int cnt   = g_degi[node];

    float4 acc = make_float4(0.f, 0.f, 0.f, 0.f);
    for (int k0 = 0; k0 < cnt; k0 += 32) {
        int kk = k0 + (int)lane;
        int2 sn = make_int2(0, 0);
        if (kk < cnt) sn = g_csr[start + kk];
        int lim = min(32, cnt - k0);
        int j = 0;
        for (; j + 4 <= lim; j += 4) {
            int s0 = __shfl_sync(0xffffffffu, sn.x, j + 0);
            int s1 = __shfl_sync(0xffffffffu, sn.x, j + 1);
            int s2 = __shfl_sync(0xffffffffu, sn.x, j + 2);
            int s3 = __shfl_sync(0xffffffffu, sn.x, j + 3);
            float n0 = __int_as_float(__shfl_sync(0xffffffffu, sn.y, j + 0));
            float n1 = __int_as_float(__shfl_sync(0xffffffffu, sn.y, j + 1));
            float n2 = __int_as_float(__shfl_sync(0xffffffffu, sn.y, j + 2));
            float n3 = __int_as_float(__shfl_sync(0xffffffffu, sn.y, j + 3));
            uint2 r0 = __ldg(reinterpret_cast<const uint2*>(srcBase + (size_t)s0 * D + c));
            uint2 r1 = __ldg(reinterpret_cast<const uint2*>(srcBase + (size_t)s1 * D + c));
            uint2 r2 = __ldg(reinterpret_cast<const uint2*>(srcBase + (size_t)s2 * D + c));
            uint2 r3 = __ldg(reinterpret_cast<const uint2*>(srcBase + (size_t)s3 * D + c));
            fma_edge(acc, n0, r0);
            fma_edge(acc, n1, r1);
            fma_edge(acc, n2, r2);
            fma_edge(acc, n3, r3);
        }
        for (; j < lim; j++) {
            int   sj = __shfl_sync(0xffffffffu, sn.x, j);
            float nj = __int_as_float(__shfl_sync(0xffffffffu, sn.y, j));
            uint2 rv = __ldg(reinterpret_cast<const uint2*>(srcBase + (size_t)sj * D + c));
            fma_edge(acc, nj, rv);
        }
    }
    __half* dstBase = (lane < 16) ? di : dp;
    __half2 o0 = __floats2half2_rn(acc.x, acc.y);
    __half2 o1 = __floats2half2_rn(acc.z, acc.w);
    uint2 outw;
    outw.x = *reinterpret_cast<unsigned*>(&o0);
    outw.y = *reinterpret_cast<unsigned*>(&o1);
    *reinterpret_cast<uint2*>(dstBase + (size_t)node * D + c) = outw;
}

// One warp per triple; acc rows computed on the fly: e0(fp32) + A + B + C (fp16).
// acc = 4 * mean, so dots scale by 1/16.
__global__ void __launch_bounds__(256)
k_score(const float* __restrict__ ei, const float* __restrict__ ep,
        const float* __restrict__ q, const float* __restrict__ bq,
        const int* __restrict__ user, const int* __restrict__ itp,
        const int* __restrict__ itn, const void* __restrict__ mask) {
    int t = blockIdx.x * blockDim.x + threadIdx.x;
    int w = t >> 5;
    int lane = t & 31;
    int wib = (threadIdx.x >> 5);
    __shared__ float sred[8][4];

    float s0 = 0.f, s1 = 0.f, s2 = 0.f, s3 = 0.f;
    if (w < BATCH) {
        int u  = user[w];
        int p  = itp[w];
        int n  = itn[w];
        size_t ru = (size_t)u * D;
        size_t rp = (size_t)(p + N_USER) * D;
        size_t rn = (size_t)(n + N_USER) * D;

        auto rowsum = [&](const float* e, const __half* a, const __half* b,
                          const __half* cc, size_t r) -> float2 {
            float2 x = reinterpret_cast<const float2*>(e + r)[lane];
            float2 fa = __half22float2(reinterpret_cast<const __half2*>(a + r)[lane]);
            float2 fb = __half22float2(reinterpret_cast<const __half2*>(b + r)[lane]);
            float2 fc = __half22float2(reinterpret_cast<const __half2*>(cc + r)[lane]);
            return make_float2(x.x + fa.x + fb.x + fc.x, x.y + fa.y + fb.y + fc.y);
        };

        float2 a  = rowsum(ei, g_A_int, g_B_int, g_C_int, ru);
        float2 bb = rowsum(ep, g_A_pop, g_B_pop, g_C_pop, ru);
        float2 cp = rowsum(ei, g_A_int, g_B_int, g_C_int, rp);
        float2 dp = rowsum(ep, g_A_pop, g_B_pop, g_C_pop, rp);
        float2 cn = rowsum(ei, g_A_int, g_B_int, g_C_int, rn);
        float2 dn = rowsum(ep, g_A_pop, g_B_pop, g_C_pop, rn);

        float pint = a.x * cp.x + a.y * cp.y;
        float nint = a.x * cn.x + a.y * cn.y;
        float ppop = bb.x * dp.x + bb.y * dp.y;
        float npop = bb.x * dn.x + bb.y * dn.y;

        #pragma unroll
        for (int o = 16; o > 0; o >>= 1) {
            pint += __shfl_xor_sync(0xffffffffu, pint, o);
            nint += __shfl_xor_sync(0xffffffffu, nint, o);
            ppop += __shfl_xor_sync(0xffffffffu, ppop, o);
            npop += __shfl_xor_sync(0xffffffffu, npop, o);
        }

        if (lane == 0) {
            const float inv16 = 0.0625f;
            pint *= inv16; nint *= inv16; ppop *= inv16; npop *= inv16;

            bool m;
            if (g_mask_is_u8)
                m = ((const unsigned char*)mask)[w] != 0;
            else
                m = ((const int*)mask)[w] != 0;
            float mf = m ? 1.0f : 0.0f;
            float nmf = 1.0f - mf;

            s0 = mf  * logsig_f(pint - nint);
            s1 = mf  * logsig_f(npop - ppop);
            s2 = nmf * logsig_f(ppop - npop);

            float popp = softplus_f(q[p]) + softplus_f(bq[p]);
            float popn = softplus_f(q[n]) + softplus_f(bq[n]);
            float ptot = pint + ppop;
            float ntot = nint + npop;
            s3 = logsig_f(tanhf(popp) * ptot - tanhf(popn) * ntot);
        }
    }
    if (lane == 0) {
        sred[wib][0] = s0; sred[wib][1] = s1; sred[wib][2] = s2; sred[wib][3] = s3;
    }
    __syncthreads();
    if (threadIdx.x < 4) {
        float tsum = 0.f;
        #pragma unroll
        for (int k = 0; k < 8; k++) tsum += sred[k][threadIdx.x];
        atomicAdd(&g_sums[threadIdx.x], (double)tsum);
    }
}

__global__ void k_final(float* __restrict__ out) {
    double invB = 1.0 / (double)BATCH;
    double s0 = g_sums[0], s1 = g_sums[1], s2 = g_sums[2], s3 = g_sums[3];
    double loss_int  = -s0 * invB;
    double loss_pop  = (-s1 + s2) * invB;
    double loss_tide = -s3 * invB;
    out[0] = (float)(0.1 * loss_int + 0.1 * loss_pop + 0.2 * loss_tide);
}

// ---------------- launch ------------------------------------------------------
extern "C" void kernel_launch(void* const* d_in, const int* in_sizes, int n_in,
                              void* d_out, int out_size) {
    const float* emb_int = (const float*)d_in[0];
    const float* emb_pop = (const float*)d_in[1];
    const float* q       = (const float*)d_in[2];
    const float* bq      = (const float*)d_in[3];
    const int*   user    = (const int*)d_in[4];
    const int*   itp     = (const int*)d_in[5];
    const int*   itn     = (const int*)d_in[6];
    const void*  mask    = d_in[7];
    const int*   es      = (const int*)d_in[8];
    const int*   ed      = (const int*)d_in[9];
    float* out = (float*)d_out;

    const int TB = 256;
    int gridE  = (E_EDGES + TB - 1) / TB;
    int gridC  = (ND / 2 + TB - 1) / TB;
    int gridG  = (int)(((long long)NN * 32 + TB - 1) / TB);
    int gridS  = (BATCH * 32 + TB - 1) / TB;

    __half *E_int, *E_pop, *A_int, *A_pop, *B_int, *B_pop, *C_int, *C_pop;
    cudaGetSymbolAddress((void**)&E_int, g_E_int);
    cudaGetSymbolAddress((void**)&E_pop, g_E_pop);
    cudaGetSymbolAddress((void**)&A_int, g_A_int);
    cudaGetSymbolAddress((void**)&A_pop, g_A_pop);
    cudaGetSymbolAddress((void**)&B_int, g_B_int);
    cudaGetSymbolAddress((void**)&B_pop, g_B_pop);
    cudaGetSymbolAddress((void**)&C_int, g_C_int);
    cudaGetSymbolAddress((void**)&C_pop, g_C_pop);

    k_init_convert<<<gridC, TB>>>(emb_int, emb_pop);
    k_degree<<<gridE, TB>>>(es, ed, (const unsigned char*)mask, user, itp, itn);
    k_scan_a<<<NB_SCAN, 256>>>();
    k_scan_bc<<<NB_SCAN, 256>>>();
    k_place<<<gridE, TB>>>(es, ed);

    k_gather<<<gridG, TB>>>(E_int, E_pop, A_int, A_pop, 0);   // layer 1
    k_gather<<<gridG, TB>>>(A_int, A_pop, B_int, B_pop, 0);   // layer 2
    k_gather<<<gridG, TB>>>(B_int, B_pop, C_int, C_pop, 1);   // layer 3 (pruned)

    k_score<<<gridS, TB>>>(emb_int, emb_pop, q, bq, user, itp, itn, mask);
    k_final<<<1, 1>>>(out);
}

// round 5
// speedup vs baseline: 3.9175x; 1.1537x over previous
#include <cuda_runtime.h>
#include <cuda_fp16.h>
#include <math.h>

// Problem constants (fixed-shape problem)
static constexpr int N_USER  = 100000;
static constexpr int N_ITEM  = 50000;
static constexpr int NN      = N_USER + N_ITEM;   // 150000
static constexpr int D       = 64;
static constexpr int ROW     = 128;               // interleaved: 64 int + 64 pop halves
static constexpr int E_EDGES = 2000000;
static constexpr int BATCH   = 8192;
static constexpr int ND      = NN * D;            // 9,600,000
static constexpr int NROW    = NN * ROW;          // 19,200,000 halves per buffer

static constexpr int SCAN_CHUNK = 1024;
static constexpr int NB_SCAN = (NN + SCAN_CHUNK - 1) / SCAN_CHUNK;  // 147

// ---------------- device scratch (static globals, no allocation) -------------
__device__ int    g_dego[NN];
__device__ int    g_degi[NN];
__device__ int    g_rowptr[NN];
__device__ int    g_cursor[NN];
__device__ int    g_bsum[NB_SCAN];
__device__ int2   g_csr[E_EDGES];          // .x = src node, .y = norm (float bits)
__device__ unsigned char g_need[NN];       // layer-3 pruning flags
__device__ __half g_E[NROW];               // interleaved fp16 emb (int | pop)
__device__ __half g_A[NROW];
__device__ __half g_B[NROW];
__device__ __half g_C[NROW];
__device__ double g_sums[4];
__device__ int    g_mask_is_u8;

// ---------------- helpers ----------------------------------------------------
__device__ __forceinline__ float softplus_f(float x) {
    return fmaxf(x, 0.0f) + log1pf(expf(-fabsf(x)));
}
__device__ __forceinline__ float logsig_f(float x) {
    return fminf(x, 0.0f) - log1pf(expf(-fabsf(x)));
}
// acc[4] of float2 += n * (8 halves in uint4)
__device__ __forceinline__ void fma8(float2* acc, float n, uint4 raw) {
    __half2 h0 = *reinterpret_cast<__half2*>(&raw.x);
    __half2 h1 = *reinterpret_cast<__half2*>(&raw.y);
    __half2 h2 = *reinterpret_cast<__half2*>(&raw.z);
    __half2 h3 = *reinterpret_cast<__half2*>(&raw.w);
    float2 f0 = __half22float2(h0);
    float2 f1 = __half22float2(h1);
    float2 f2 = __half22float2(h2);
    float2 f3 = __half22float2(h3);
    acc[0].x += n * f0.x; acc[0].y += n * f0.y;
    acc[1].x += n * f1.x; acc[1].y += n * f1.y;
    acc[2].x += n * f2.x; acc[2].y += n * f2.y;
    acc[3].x += n * f3.x; acc[3].y += n * f3.y;
}

// ---------------- kernels ----------------------------------------------------
// Fused: fp32->fp16 interleaved conversion + zero degrees/flags/sums.
// i indexes output half2 (NROW/2 = NN*64 of them).
__global__ void k_init_convert(const float* __restrict__ ei, const float* __restrict__ ep) {
    int i = blockIdx.x * blockDim.x + threadIdx.x;
    if (i < NROW / 2) {
        int node = i >> 6;          // 64 half2 per row
        int col2 = i & 63;          // which half2 within row
        const float* s = (col2 < 32) ? (ei + (size_t)node * D + col2 * 2)
                                     : (ep + (size_t)node * D + (col2 - 32) * 2);
        float2 v = *reinterpret_cast<const float2*>(s);
        reinterpret_cast<__half2*>(g_E)[i] = __floats2half2_rn(v.x, v.y);
    }
    if (i < NN) { g_dego[i] = 0; g_degi[i] = 0; g_need[i] = 0; }
    if (i < 4)  g_sums[i] = 0.0;
    if (i == 0) g_mask_is_u8 = 0;
}

// Degree counting + mask-layout detect + layer-3 need flags.
__global__ void k_degree(const int* __restrict__ es, const int* __restrict__ ed,
                         const unsigned char* __restrict__ m,
                         const int* __restrict__ user, const int* __restrict__ itp,
                         const int* __restrict__ itn) {
    int i = blockIdx.x * blockDim.x + threadIdx.x;
    if (i < BATCH) {
        if ((i & 3) && m[i]) atomicOr(&g_mask_is_u8, 1);
        g_need[user[i]] = 1;
        g_need[itp[i] + N_USER] = 1;
        g_need[itn[i] + N_USER] = 1;
    }
    if (i >= E_EDGES) return;
    atomicAdd(&g_dego[es[i]], 1);
    atomicAdd(&g_degi[ed[i]], 1);
}

// Per-chunk sums of g_degi.
__global__ void k_scan_a() {
    __shared__ int sdata[256];
    int base = blockIdx.x * SCAN_CHUNK;
    int t = threadIdx.x;
    int s = 0;
    #pragma unroll
    for (int j = 0; j < 4; j++) {
        int idx = base + t * 4 + j;
        if (idx < NN) s += g_degi[idx];
    }
    sdata[t] = s;
    __syncthreads();
    for (int off = 128; off > 0; off >>= 1) {
        if (t < off) sdata[t] += sdata[t + off];
        __syncthreads();
    }
    if (t == 0) g_bsum[blockIdx.x] = sdata[0];
}

// Fused: each block redundantly scans block sums, then writes its rowptr range.
__global__ void k_scan_bc() {
    __shared__ int sb[256];
    __shared__ int sdata[256];
    int t = threadIdx.x;

    sb[t] = (t < NB_SCAN) ? g_bsum[t] : 0;
    __syncthreads();
    for (int off = 1; off < 256; off <<= 1) {
        int tmp = (t >= off) ? sb[t - off] : 0;
        __syncthreads();
        sb[t] += tmp;
        __syncthreads();
    }
    int boff = (blockIdx.x == 0) ? 0 : sb[blockIdx.x - 1];

    int base = blockIdx.x * SCAN_CHUNK;
    int v[4];
    int tsum = 0;
    #pragma unroll
    for (int j = 0; j < 4; j++) {
        int idx = base + t * 4 + j;
        v[j] = (idx < NN) ? g_degi[idx] : 0;
        tsum += v[j];
    }
    sdata[t] = tsum;
    __syncthreads();
    for (int off = 1; off < 256; off <<= 1) {
        int tmp = (t >= off) ? sdata[t - off] : 0;
        __syncthreads();
        sdata[t] += tmp;
        __syncthreads();
    }
    int run = sdata[t] - tsum + boff;
    #pragma unroll
    for (int j = 0; j < 4; j++) {
        int idx = base + t * 4 + j;
        if (idx < NN) {
            g_rowptr[idx] = run;
            g_cursor[idx] = run;
            run += v[j];
        }
    }
}

// Edge placement; norm computed from degrees; packed (src, norm) write.
__global__ void k_place(const int* __restrict__ es, const int* __restrict__ ed) {
    int i = blockIdx.x * blockDim.x + threadIdx.x;
    if (i >= E_EDGES) return;
    int s = es[i];
    int d = ed[i];
    int pos = atomicAdd(&g_cursor[d], 1);
    float nm = rsqrtf(fmaxf((float)g_dego[s], 1.0f))
             * rsqrtf(fmaxf((float)g_degi[d], 1.0f));
    g_csr[pos] = make_int2(s, __float_as_int(nm));
}

// CSR gather: 16 lanes per node, 2 nodes per warp.
// Each lane loads uint4 (16B = 8 halves) of the interleaved 256B row.
// fp16 source, fp32 accumulate, fp16 store. prune != 0: skip nodes not in g_need.
__global__ void __launch_bounds__(256)
k_gather(const __half* __restrict__ src, __half* __restrict__ dst, int prune) {
    unsigned t = blockIdx.x * blockDim.x + threadIdx.x;
    unsigned warp = t >> 5;
    unsigned lane = t & 31u;
    unsigned grp  = lane >> 4;      // 0 or 1
    unsigned gl   = lane & 15u;     // lane within group
    unsigned node = warp * 2 + grp;
    if (node >= (unsigned)NN) return;
    if (prune && !g_need[node]) return;

    const unsigned gmask = 0xFFFFu << (grp * 16);
    const int gbase = grp * 16;
    const int c = gl * 8;           // half offset within 128-half row

    int start = g_rowptr[node];
    int cnt   = g_degi[node];

    float2 acc[4];
    acc[0] = make_float2(0.f, 0.f); acc[1] = make_float2(0.f, 0.f);
    acc[2] = make_float2(0.f, 0.f); acc[3] = make_float2(0.f, 0.f);

    for (int k0 = 0; k0 < cnt; k0 += 16) {
        int kk = k0 + (int)gl;
        int2 sn = make_int2(0, 0);
        if (kk < cnt) sn = g_csr[start + kk];
        int lim = min(16, cnt - k0);
        int j = 0;
        for (; j + 4 <= lim; j += 4) {
            int s0 = __shfl_sync(gmask, sn.x, gbase + j + 0);
            int s1 = __shfl_sync(gmask, sn.x, gbase + j + 1);
            int s2 = __shfl_sync(gmask, sn.x, gbase + j + 2);
            int s3 = __shfl_sync(gmask, sn.x, gbase + j + 3);
            float n0 = __int_as_float(__shfl_sync(gmask, sn.y, gbase + j + 0));
            float n1 = __int_as_float(__shfl_sync(gmask, sn.y, gbase + j + 1));
            float n2 = __int_as_float(__shfl_sync(gmask, sn.y, gbase + j + 2));
            float n3 = __int_as_float(__shfl_sync(gmask, sn.y, gbase + j + 3));
            uint4 r0 = __ldg(reinterpret_cast<const uint4*>(src + (size_t)s0 * ROW + c));
            uint4 r1 = __ldg(reinterpret_cast<const uint4*>(src + (size_t)s1 * ROW + c));
            uint4 r2 = __ldg(reinterpret_cast<const uint4*>(src + (size_t)s2 * ROW + c));
            uint4 r3 = __ldg(reinterpret_cast<const uint4*>(src + (size_t)s3 * ROW + c));
            fma8(acc, n0, r0);
            fma8(acc, n1, r1);
            fma8(acc, n2, r2);
            fma8(acc, n3, r3);
        }
        for (; j < lim; j++) {
            int   sj = __shfl_sync(gmask, sn.x, gbase + j);
            float nj = __int_as_float(__shfl_sync(gmask, sn.y, gbase + j));
            uint4 rv = __ldg(reinterpret_cast<const uint4*>(src + (size_t)sj * ROW + c));
            fma8(acc, nj, rv);
        }
    }

    __half2 o0 = __floats2half2_rn(acc[0].x, acc[0].y);
    __half2 o1 = __floats2half2_rn(acc[1].x, acc[1].y);
    __half2 o2 = __floats2half2_rn(acc[2].x, acc[2].y);
    __half2 o3 = __floats2half2_rn(acc[3].x, acc[3].y);
    uint4 outw;
    outw.x = *reinterpret_cast<unsigned*>(&o0);
    outw.y = *reinterpret_cast<unsigned*>(&o1);
    outw.z = *reinterpret_cast<unsigned*>(&o2);
    outw.w = *reinterpret_cast<unsigned*>(&o3);
    *reinterpret_cast<uint4*>(dst + (size_t)node * ROW + c) = outw;
}

// One warp per triple; acc rows computed on the fly: e0(fp32) + A + B + C (fp16,
// interleaved rows). acc = 4 * mean, so dots scale by 1/16.
__global__ void __launch_bounds__(256)
k_score(const float* __restrict__ ei, const float* __restrict__ ep,
        const float* __restrict__ q, const float* __restrict__ bq,
        const int* __restrict__ user, const int* __restrict__ itp,
        const int* __restrict__ itn, const void* __restrict__ mask) {
    int t = blockIdx.x * blockDim.x + threadIdx.x;
    int w = t >> 5;
    int lane = t & 31;
    int wib = (threadIdx.x >> 5);
    __shared__ float sred[8][4];

    float s0 = 0.f, s1 = 0.f, s2 = 0.f, s3 = 0.f;
    if (w < BATCH) {
        int u  = user[w];
        int p  = itp[w];
        int n  = itn[w];

        // pop=0: int half (row offset 0), pop=1: pop half (row offset 64)
        auto rowsum = [&](const float* e, int node, int pop) -> float2 {
            size_t re = (size_t)node * D;
            size_t rh = (size_t)node * ROW + pop * 64;
            float2 x = reinterpret_cast<const float2*>(e + re)[lane];
            float2 fa = __half22float2(*reinterpret_cast<const __half2*>(g_A + rh + lane * 2));
            float2 fb = __half22float2(*reinterpret_cast<const __half2*>(g_B + rh + lane * 2));
            float2 fc = __half22float2(*reinterpret_cast<const __half2*>(g_C + rh + lane * 2));
            return make_float2(x.x + fa.x + fb.x + fc.x, x.y + fa.y + fb.y + fc.y);
        };

        int np = p + N_USER;
        int nn = n + N_USER;
        float2 a  = rowsum(ei, u, 0);
        float2 bb = rowsum(ep, u, 1);
        float2 cp = rowsum(ei, np, 0);
        float2 dp = rowsum(ep, np, 1);
        float2 cn = rowsum(ei, nn, 0);
        float2 dn = rowsum(ep, nn, 1);

        float pint = a.x * cp.x + a.y * cp.y;
        float nint = a.x * cn.x + a.y * cn.y;
        float ppop = bb.x * dp.x + bb.y * dp.y;
        float npop = bb.x * dn.x + bb.y * dn.y;

        #pragma unroll
        for (int o = 16; o > 0; o >>= 1) {
            pint += __shfl_xor_sync(0xffffffffu, pint, o);
            nint += __shfl_xor_sync(0xffffffffu, nint, o);
            ppop += __shfl_xor_sync(0xffffffffu, ppop, o);
            npop += __shfl_xor_sync(0xffffffffu, npop, o);
        }

        if (lane == 0) {
            const float inv16 = 0.0625f;
            pint *= inv16; nint *= inv16; ppop *= inv16; npop *= inv16;

            bool m;
            if (g_mask_is_u8)
                m = ((const unsigned char*)mask)[w] != 0;
            else
                m = ((const int*)mask)[w] != 0;
            float mf = m ? 1.0f : 0.0f;
            float nmf = 1.0f - mf;

            s0 = mf  * logsig_f(pint - nint);
            s1 = mf  * logsig_f(npop - ppop);
            s2 = nmf * logsig_f(ppop - npop);

            float popp = softplus_f(q[p]) + softplus_f(bq[p]);
            float popn = softplus_f(q[n]) + softplus_f(bq[n]);
            float ptot = pint + ppop;
            float ntot = nint + npop;
            s3 = logsig_f(tanhf(popp) * ptot - tanhf(popn) * ntot);
        }
    }
    if (lane == 0) {
        sred[wib][0] = s0; sred[wib][1] = s1; sred[wib][2] = s2; sred[wib][3] = s3;
    }
    __syncthreads();
    if (threadIdx.x < 4) {
        float tsum = 0.f;
        #pragma unroll
        for (int k = 0; k < 8; k++) tsum += sred[k][threadIdx.x];
        atomicAdd(&g_sums[threadIdx.x], (double)tsum);
    }
}

__global__ void k_final(float* __restrict__ out) {
    double invB = 1.0 / (double)BATCH;
    double s0 = g_sums[0], s1 = g_sums[1], s2 = g_sums[2], s3 = g_sums[3];
    double loss_int  = -s0 * invB;
    double loss_pop  = (-s1 + s2) * invB;
    double loss_tide = -s3 * invB;
    out[0] = (float)(0.1 * loss_int + 0.1 * loss_pop + 0.2 * loss_tide);
}

// ---------------- launch ------------------------------------------------------
extern "C" void kernel_launch(void* const* d_in, const int* in_sizes, int n_in,
                              void* d_out, int out_size) {
    const float* emb_int = (const float*)d_in[0];
    const float* emb_pop = (const float*)d_in[1];
    const float* q       = (const float*)d_in[2];
    const float* bq      = (const float*)d_in[3];
    const int*   user    = (const int*)d_in[4];
    const int*   itp     = (const int*)d_in[5];
    const int*   itn     = (const int*)d_in[6];
    const void*  mask    = d_in[7];
    const int*   es      = (const int*)d_in[8];
    const int*   ed      = (const int*)d_in[9];
    float* out = (float*)d_out;

    const int TB = 256;
    int gridE  = (E_EDGES + TB - 1) / TB;
    int gridC  = (NROW / 2 + TB - 1) / TB;
    long long warpsG = (NN + 1) / 2;
    int gridG  = (int)((warpsG * 32 + TB - 1) / TB);
    int gridS  = (BATCH * 32 + TB - 1) / TB;

    __half *E, *A, *B, *C;
    cudaGetSymbolAddress((void**)&E, g_E);
    cudaGetSymbolAddress((void**)&A, g_A);
    cudaGetSymbolAddress((void**)&B, g_B);
    cudaGetSymbolAddress((void**)&C, g_C);

    k_init_convert<<<gridC, TB>>>(emb_int, emb_pop);
    k_degree<<<gridE, TB>>>(es, ed, (const unsigned char*)mask, user, itp, itn);
    k_scan_a<<<NB_SCAN, 256>>>();
    k_scan_bc<<<NB_SCAN, 256>>>();
    k_place<<<gridE, TB>>>(es, ed);

    k_gather<<<gridG, TB>>>(E, A, 0);   // layer 1
    k_gather<<<gridG, TB>>>(A, B, 0);   // layer 2
    k_gather<<<gridG, TB>>>(B, C, 1);   // layer 3 (pruned)

    k_score<<<gridS, TB>>>(emb_int, emb_pop, q, bq, user, itp, itn, mask);
    k_final<<<1, 1>>>(out);
}

// round 6
// speedup vs baseline: 4.8337x; 1.2339x over previous
#include <cuda_runtime.h>
#include <cuda_fp16.h>
#include <math.h>

// Problem constants (fixed-shape problem)
static constexpr int N_USER  = 100000;
static constexpr int N_ITEM  = 50000;
static constexpr int NN      = N_USER + N_ITEM;   // 150000
static constexpr int D       = 64;
static constexpr int ROW     = 128;               // interleaved: 64 int + 64 pop halves
static constexpr int E_EDGES = 2000000;
static constexpr int BATCH   = 8192;
static constexpr int NROW    = NN * ROW;          // 19,200,000 halves per buffer

static constexpr int SCAN_CHUNK = 1024;
static constexpr int NB_SCAN = (NN + SCAN_CHUNK - 1) / SCAN_CHUNK;  // 147

// ---------------- device scratch (static globals, no allocation) -------------
__device__ int    g_dego[NN];
__device__ int    g_degi[NN];
__device__ int    g_rowptr[NN];
__device__ int    g_cursor[NN];
__device__ int    g_bsum[NB_SCAN];
__device__ int    g_csr[E_EDGES];          // src node only (norm factored out)
__device__ unsigned char g_need[NN];       // layer-3 pruning flags
__device__ __half g_E[NROW];               // S0 = rdo * emb (interleaved int|pop)
__device__ __half g_A[NROW];               // S1 = rdo*rdi*sum1
__device__ __half g_B[NROW];               // S2
__device__ __half g_C[NROW];               // S3
__device__ double g_sums[4];
__device__ int    g_mask_is_u8;

// ---------------- helpers ----------------------------------------------------
__device__ __forceinline__ float softplus_f(float x) {
    return fmaxf(x, 0.0f) + log1pf(expf(-fabsf(x)));
}
__device__ __forceinline__ float logsig_f(float x) {
    return fminf(x, 0.0f) - log1pf(expf(-fabsf(x)));
}
// acch[4] (half2) += 8 halves in uint4
__device__ __forceinline__ void hadd8(__half2* acch, uint4 raw) {
    acch[0] = __hadd2(acch[0], *reinterpret_cast<__half2*>(&raw.x));
    acch[1] = __hadd2(acch[1], *reinterpret_cast<__half2*>(&raw.y));
    acch[2] = __hadd2(acch[2], *reinterpret_cast<__half2*>(&raw.z));
    acch[3] = __hadd2(acch[3], *reinterpret_cast<__half2*>(&raw.w));
}

// ---------------- kernels ----------------------------------------------------
// Zero degrees / flags / sums.
__global__ void k_init() {
    int i = blockIdx.x * blockDim.x + threadIdx.x;
    if (i < NN) { g_dego[i] = 0; g_degi[i] = 0; g_need[i] = 0; }
    if (i < 4)  g_sums[i] = 0.0;
    if (i == 0) g_mask_is_u8 = 0;
}

// Degree counting + mask-layout detect + layer-3 need flags.
__global__ void k_degree(const int* __restrict__ es, const int* __restrict__ ed,
                         const unsigned char* __restrict__ m,
                         const int* __restrict__ user, const int* __restrict__ itp,
                         const int* __restrict__ itn) {
    int i = blockIdx.x * blockDim.x + threadIdx.x;
    if (i < BATCH) {
        if ((i & 3) && m[i]) atomicOr(&g_mask_is_u8, 1);
        g_need[user[i]] = 1;
        g_need[itp[i] + N_USER] = 1;
        g_need[itn[i] + N_USER] = 1;
    }
    if (i >= E_EDGES) return;
    atomicAdd(&g_dego[es[i]], 1);
    atomicAdd(&g_degi[ed[i]], 1);
}

// fp32 -> fp16 interleaved conversion, pre-scaled by rdo[node].
__global__ void k_convert(const float* __restrict__ ei, const float* __restrict__ ep) {
    int i = blockIdx.x * blockDim.x + threadIdx.x;
    if (i >= NROW / 2) return;
    int node = i >> 6;          // 64 half2 per row
    int col2 = i & 63;
    float rdo = rsqrtf(fmaxf((float)g_dego[node], 1.0f));
    const float* s = (col2 < 32) ? (ei + (size_t)node * D + col2 * 2)
                                 : (ep + (size_t)node * D + (col2 - 32) * 2);
    float2 v = *reinterpret_cast<const float2*>(s);
    reinterpret_cast<__half2*>(g_E)[i] = __floats2half2_rn(v.x * rdo, v.y * rdo);
}

// Per-chunk sums of g_degi.
__global__ void k_scan_a() {
    __shared__ int sdata[256];
    int base = blockIdx.x * SCAN_CHUNK;
    int t = threadIdx.x;
    int s = 0;
    #pragma unroll
    for (int j = 0; j < 4; j++) {
        int idx = base + t * 4 + j;
        if (idx < NN) s += g_degi[idx];
    }
    sdata[t] = s;
    __syncthreads();
    for (int off = 128; off > 0; off >>= 1) {
        if (t < off) sdata[t] += sdata[t + off];
        __syncthreads();
    }
    if (t == 0) g_bsum[blockIdx.x] = sdata[0];
}

// Fused: each block redundantly scans block sums, then writes its rowptr range.
__global__ void k_scan_bc() {
    __shared__ int sb[256];
    __shared__ int sdata[256];
    int t = threadIdx.x;

    sb[t] = (t < NB_SCAN) ? g_bsum[t] : 0;
    __syncthreads();
    for (int off = 1; off < 256; off <<= 1) {
        int tmp = (t >= off) ? sb[t - off] : 0;
        __syncthreads();
        sb[t] += tmp;
        __syncthreads();
    }
    int boff = (blockIdx.x == 0) ? 0 : sb[blockIdx.x - 1];

    int base = blockIdx.x * SCAN_CHUNK;
    int v[4];
    int tsum = 0;
    #pragma unroll
    for (int j = 0; j < 4; j++) {
        int idx = base + t * 4 + j;
        v[j] = (idx < NN) ? g_degi[idx] : 0;
        tsum += v[j];
    }
    sdata[t] = tsum;
    __syncthreads();
    for (int off = 1; off < 256; off <<= 1) {
        int tmp = (t >= off) ? sdata[t - off] : 0;
        __syncthreads();
        sdata[t] += tmp;
        __syncthreads();
    }
    int run = sdata[t] - tsum + boff;
    #pragma unroll
    for (int j = 0; j < 4; j++) {
        int idx = base + t * 4 + j;
        if (idx < NN) {
            g_rowptr[idx] = run;
            g_cursor[idx] = run;
            run += v[j];
        }
    }
}

// Edge placement (src index only; norm factored into buffer scaling).
__global__ void k_place(const int* __restrict__ es, const int* __restrict__ ed) {
    int i = blockIdx.x * blockDim.x + threadIdx.x;
    if (i >= E_EDGES) return;
    int s = es[i];
    int d = ed[i];
    int pos = atomicAdd(&g_cursor[d], 1);
    g_csr[pos] = s;
}

// CSR gather: 16 lanes per node, 2 nodes per warp.
// Inner loop: pure fp16 row sum (sources are pre-scaled by rdo; rdi*rdo applied
// at store). Each lane loads uint4 (16B = 8 halves) of the interleaved row.
// prune != 0: skip nodes not in g_need.
__global__ void __launch_bounds__(256)
k_gather(const __half* __restrict__ src, __half* __restrict__ dst, int prune) {
    unsigned t = blockIdx.x * blockDim.x + threadIdx.x;
    unsigned warp = t >> 5;
    unsigned lane = t & 31u;
    unsigned grp  = lane >> 4;      // 0 or 1
    unsigned gl   = lane & 15u;     // lane within group
    unsigned node = warp * 2 + grp;
    if (node >= (unsigned)NN) return;
    if (prune && !g_need[node]) return;

    const unsigned gmask = 0xFFFFu << (grp * 16);
    const int gbase = grp * 16;
    const int c = gl * 8;           // half offset within 128-half row

    int start = g_rowptr[node];
    int cnt   = g_degi[node];

    __half2 zz = __floats2half2_rn(0.f, 0.f);
    __half2 acch[4] = { zz, zz, zz, zz };

    for (int k0 = 0; k0 < cnt; k0 += 16) {
        int kk = k0 + (int)gl;
        int sidx = 0;
        if (kk < cnt) sidx = g_csr[start + kk];
        int lim = min(16, cnt - k0);
        int j = 0;
        for (; j + 4 <= lim; j += 4) {
            int s0 = __shfl_sync(gmask, sidx, gbase + j + 0);
            int s1 = __shfl_sync(gmask, sidx, gbase + j + 1);
            int s2 = __shfl_sync(gmask, sidx, gbase + j + 2);
            int s3 = __shfl_sync(gmask, sidx, gbase + j + 3);
            uint4 r0 = __ldg(reinterpret_cast<const uint4*>(src + (size_t)s0 * ROW + c));
            uint4 r1 = __ldg(reinterpret_cast<const uint4*>(src + (size_t)s1 * ROW + c));
            uint4 r2 = __ldg(reinterpret_cast<const uint4*>(src + (size_t)s2 * ROW + c));
            uint4 r3 = __ldg(reinterpret_cast<const uint4*>(src + (size_t)s3 * ROW + c));
            hadd8(acch, r0);
            hadd8(acch, r1);
            hadd8(acch, r2);
            hadd8(acch, r3);
        }
        for (; j < lim; j++) {
            int sj = __shfl_sync(gmask, sidx, gbase + j);
            uint4 rv = __ldg(reinterpret_cast<const uint4*>(src + (size_t)sj * ROW + c));
            hadd8(acch, rv);
        }
    }

    // Apply per-node factor rdo[d]*rdi[d] in fp32, store fp16.
    float rs = rsqrtf(fmaxf((float)g_dego[node], 1.0f))
             * rsqrtf(fmaxf((float)g_degi[node], 1.0f));
    uint4 outw;
    #pragma unroll
    for (int i2 = 0; i2 < 4; i2++) {
        float2 f = __half22float2(acch[i2]);
        __half2 o = __floats2half2_rn(f.x * rs, f.y * rs);
        (&outw.x)[i2] = *reinterpret_cast<unsigned*>(&o);
    }
    *reinterpret_cast<uint4*>(dst + (size_t)node * ROW + c) = outw;
}

// One warp per triple. f-row (×4) = e0 + sqrt(dego[node]) * (S_A + S_B + S_C).
// Dots scale by 1/16.
__global__ void __launch_bounds__(256)
k_score(const float* __restrict__ ei, const float* __restrict__ ep,
        const float* __restrict__ q, const float* __restrict__ bq,
        const int* __restrict__ user, const int* __restrict__ itp,
        const int* __restrict__ itn, const void* __restrict__ mask) {
    int t = blockIdx.x * blockDim.x + threadIdx.x;
    int w = t >> 5;
    int lane = t & 31;
    int wib = (threadIdx.x >> 5);
    __shared__ float sred[8][4];

    float s0 = 0.f, s1 = 0.f, s2 = 0.f, s3 = 0.f;
    if (w < BATCH) {
        int u  = user[w];
        int p  = itp[w];
        int n  = itn[w];

        auto rowsum = [&](const float* e, int node, int pop) -> float2 {
            size_t re = (size_t)node * D;
            size_t rh = (size_t)node * ROW + pop * 64;
            float sq = sqrtf(fmaxf((float)g_dego[node], 1.0f));
            float2 x = reinterpret_cast<const float2*>(e + re)[lane];
            float2 fa = __half22float2(*reinterpret_cast<const __half2*>(g_A + rh + lane * 2));
            float2 fb = __half22float2(*reinterpret_cast<const __half2*>(g_B + rh + lane * 2));
            float2 fc = __half22float2(*reinterpret_cast<const __half2*>(g_C + rh + lane * 2));
            return make_float2(x.x + sq * (fa.x + fb.x + fc.x),
                               x.y + sq * (fa.y + fb.y + fc.y));
        };

        int np = p + N_USER;
        int nn = n + N_USER;
        float2 a  = rowsum(ei, u, 0);
        float2 bb = rowsum(ep, u, 1);
        float2 cp = rowsum(ei, np, 0);
        float2 dp = rowsum(ep, np, 1);
        float2 cn = rowsum(ei, nn, 0);
        float2 dn = rowsum(ep, nn, 1);

        float pint = a.x * cp.x + a.y * cp.y;
        float nint = a.x * cn.x + a.y * cn.y;
        float ppop = bb.x * dp.x + bb.y * dp.y;
        float npop = bb.x * dn.x + bb.y * dn.y;

        #pragma unroll
        for (int o = 16; o > 0; o >>= 1) {
            pint += __shfl_xor_sync(0xffffffffu, pint, o);
            nint += __shfl_xor_sync(0xffffffffu, nint, o);
            ppop += __shfl_xor_sync(0xffffffffu, ppop, o);
            npop += __shfl_xor_sync(0xffffffffu, npop, o);
        }

        if (lane == 0) {
            const float inv16 = 0.0625f;
            pint *= inv16; nint *= inv16; ppop *= inv16; npop *= inv16;

            bool m;
            if (g_mask_is_u8)
                m = ((const unsigned char*)mask)[w] != 0;
            else
                m = ((const int*)mask)[w] != 0;
            float mf = m ? 1.0f : 0.0f;
            float nmf = 1.0f - mf;

            s0 = mf  * logsig_f(pint - nint);
            s1 = mf  * logsig_f(npop - ppop);
            s2 = nmf * logsig_f(ppop - npop);

            float popp = softplus_f(q[p]) + softplus_f(bq[p]);
            float popn = softplus_f(q[n]) + softplus_f(bq[n]);
            float ptot = pint + ppop;
            float ntot = nint + npop;
            s3 = logsig_f(tanhf(popp) * ptot - tanhf(popn) * ntot);
        }
    }
    if (lane == 0) {
        sred[wib][0] = s0; sred[wib][1] = s1; sred[wib][2] = s2; sred[wib][3] = s3;
    }
    __syncthreads();
    if (threadIdx.x < 4) {
        float tsum = 0.f;
        #pragma unroll
        for (int k = 0; k < 8; k++) tsum += sred[k][threadIdx.x];
        atomicAdd(&g_sums[threadIdx.x], (double)tsum);
    }
}

__global__ void k_final(float* __restrict__ out) {
    double invB = 1.0 / (double)BATCH;
    double s0 = g_sums[0], s1 = g_sums[1], s2 = g_sums[2], s3 = g_sums[3];
    double loss_int  = -s0 * invB;
    double loss_pop  = (-s1 + s2) * invB;
    double loss_tide = -s3 * invB;
    out[0] = (float)(0.1 * loss_int + 0.1 * loss_pop + 0.2 * loss_tide);
}

// ---------------- launch ------------------------------------------------------
extern "C" void kernel_launch(void* const* d_in, const int* in_sizes, int n_in,
                              void* d_out, int out_size) {
    const float* emb_int = (const float*)d_in[0];
    const float* emb_pop = (const float*)d_in[1];
    const float* q       = (const float*)d_in[2];
    const float* bq      = (const float*)d_in[3];
    const int*   user    = (const int*)d_in[4];
    const int*   itp     = (const int*)d_in[5];
    const int*   itn     = (const int*)d_in[6];
    const void*  mask    = d_in[7];
    const int*   es      = (const int*)d_in[8];
    const int*   ed      = (const int*)d_in[9];
    float* out = (float*)d_out;

    const int TB = 256;
    int gridE  = (E_EDGES + TB - 1) / TB;
    int gridN  = (NN + TB - 1) / TB;
    int gridC  = (NROW / 2 + TB - 1) / TB;
    long long warpsG = (NN + 1) / 2;
    int gridG  = (int)((warpsG * 32 + TB - 1) / TB);
    int gridS  = (BATCH * 32 + TB - 1) / TB;

    __half *E, *A, *B, *C;
    cudaGetSymbolAddress((void**)&E, g_E);
    cudaGetSymbolAddress((void**)&A, g_A);
    cudaGetSymbolAddress((void**)&B, g_B);
    cudaGetSymbolAddress((void**)&C, g_C);

    k_init<<<gridN, TB>>>();
    k_degree<<<gridE, TB>>>(es, ed, (const unsigned char*)mask, user, itp, itn);
    k_convert<<<gridC, TB>>>(emb_int, emb_pop);
    k_scan_a<<<NB_SCAN, 256>>>();
    k_scan_bc<<<NB_SCAN, 256>>>();
    k_place<<<gridE, TB>>>(es, ed);

    k_gather<<<gridG, TB>>>(E, A, 0);   // layer 1
    k_gather<<<gridG, TB>>>(A, B, 0);   // layer 2
    k_gather<<<gridG, TB>>>(B, C, 1);   // layer 3 (pruned)

    k_score<<<gridS, TB>>>(emb_int, emb_pop, q, bq, user, itp, itn, mask);
    k_final<<<1, 1>>>(out);
}

// round 7
// speedup vs baseline: 5.5200x; 1.1420x over previous
#include <cuda_runtime.h>
#include <cuda_fp16.h>
#include <cuda_fp8.h>
#include <math.h>

// Problem constants (fixed-shape problem)
static constexpr int N_USER  = 100000;
static constexpr int N_ITEM  = 50000;
static constexpr int NN      = N_USER + N_ITEM;   // 150000
static constexpr int D       = 64;
static constexpr int ROWB    = 128;               // row bytes: 64 int + 64 pop e4m3
static constexpr int E_EDGES = 2000000;
static constexpr int BATCH   = 8192;

static constexpr int SCAN_CHUNK = 1024;
static constexpr int NB_SCAN = (NN + SCAN_CHUNK - 1) / SCAN_CHUNK;  // 147

// All fp8 buffers store 16x the true value (descaled in k_score).
// ---------------- device scratch (static globals, no allocation) -------------
__device__ int    g_dego[NN];
__device__ int    g_degi[NN];
__device__ int    g_rowptr[NN];
__device__ int    g_cursor[NN];
__device__ int    g_bsum[NB_SCAN];
__device__ int    g_csr[E_EDGES];              // src node only (norm factored out)
__device__ unsigned char g_need[NN];           // layer-3 pruning flags
__device__ unsigned char g_E[(size_t)NN * ROWB];   // 16*rdo*emb  (e4m3)
__device__ unsigned char g_A[(size_t)NN * ROWB];
__device__ unsigned char g_B[(size_t)NN * ROWB];
__device__ unsigned char g_C[(size_t)NN * ROWB];
__device__ double g_sums[4];
__device__ int    g_mask_is_u8;

// ---------------- helpers ----------------------------------------------------
__device__ __forceinline__ float softplus_f(float x) {
    return fmaxf(x, 0.0f) + log1pf(expf(-fabsf(x)));
}
__device__ __forceinline__ float logsig_f(float x) {
    return fminf(x, 0.0f) - log1pf(expf(-fabsf(x)));
}
// acch[4] (half2) += 8 e4m3 values packed in uint2
__device__ __forceinline__ void acc_fp8_8(__half2* acch, uint2 raw) {
    __half2_raw h0 = __nv_cvt_fp8x2_to_halfraw2((__nv_fp8x2_storage_t)(raw.x & 0xFFFFu), __NV_E4M3);
    __half2_raw h1 = __nv_cvt_fp8x2_to_halfraw2((__nv_fp8x2_storage_t)(raw.x >> 16), __NV_E4M3);
    __half2_raw h2 = __nv_cvt_fp8x2_to_halfraw2((__nv_fp8x2_storage_t)(raw.y & 0xFFFFu), __NV_E4M3);
    __half2_raw h3 = __nv_cvt_fp8x2_to_halfraw2((__nv_fp8x2_storage_t)(raw.y >> 16), __NV_E4M3);
    acch[0] = __hadd2(acch[0], *reinterpret_cast<__half2*>(&h0));
    acch[1] = __hadd2(acch[1], *reinterpret_cast<__half2*>(&h1));
    acch[2] = __hadd2(acch[2], *reinterpret_cast<__half2*>(&h2));
    acch[3] = __hadd2(acch[3], *reinterpret_cast<__half2*>(&h3));
}
__device__ __forceinline__ float2 fp8x2_to_float2(unsigned short v) {
    __half2_raw h = __nv_cvt_fp8x2_to_halfraw2((__nv_fp8x2_storage_t)v, __NV_E4M3);
    return __half22float2(*reinterpret_cast<__half2*>(&h));
}

// ---------------- kernels ----------------------------------------------------
// Zero degrees / flags / sums.
__global__ void k_init() {
    int i = blockIdx.x * blockDim.x + threadIdx.x;
    if (i < NN) { g_dego[i] = 0; g_degi[i] = 0; g_need[i] = 0; }
    if (i < 4)  g_sums[i] = 0.0;
    if (i == 0) g_mask_is_u8 = 0;
}

// Degree counting + mask-layout detect + layer-3 need flags.
__global__ void k_degree(const int* __restrict__ es, const int* __restrict__ ed,
                         const unsigned char* __restrict__ m,
                         const int* __restrict__ user, const int* __restrict__ itp,
                         const int* __restrict__ itn) {
    int i = blockIdx.x * blockDim.x + threadIdx.x;
    if (i < BATCH) {
        if ((i & 3) && m[i]) atomicOr(&g_mask_is_u8, 1);
        g_need[user[i]] = 1;
        g_need[itp[i] + N_USER] = 1;
        g_need[itn[i] + N_USER] = 1;
    }
    if (i >= E_EDGES) return;
    atomicAdd(&g_dego[es[i]], 1);
    atomicAdd(&g_degi[ed[i]], 1);
}

// Per-chunk sums of g_degi.
__global__ void k_scan_a() {
    __shared__ int sdata[256];
    int base = blockIdx.x * SCAN_CHUNK;
    int t = threadIdx.x;
    int s = 0;
    #pragma unroll
    for (int j = 0; j < 4; j++) {
        int idx = base + t * 4 + j;
        if (idx < NN) s += g_degi[idx];
    }
    sdata[t] = s;
    __syncthreads();
    for (int off = 128; off > 0; off >>= 1) {
        if (t < off) sdata[t] += sdata[t + off];
        __syncthreads();
    }
    if (t == 0) g_bsum[blockIdx.x] = sdata[0];
}

// Fused: blocks [0, NB_SCAN) build rowptr/cursor; ALL blocks also run the
// grid-stride fp32 -> e4m3 (x16*rdo) conversion of the interleaved embeddings.
__global__ void k_scan_bc_convert(const float* __restrict__ ei, const float* __restrict__ ep) {
    __shared__ int sb[256];
    __shared__ int sdata[256];
    int t = threadIdx.x;

    if (blockIdx.x < NB_SCAN) {
        sb[t] = (t < NB_SCAN) ? g_bsum[t] : 0;
        __syncthreads();
        for (int off = 1; off < 256; off <<= 1) {
            int tmp = (t >= off) ? sb[t - off] : 0;
            __syncthreads();
            sb[t] += tmp;
            __syncthreads();
        }
        int boff = (blockIdx.x == 0) ? 0 : sb[blockIdx.x - 1];

        int base = blockIdx.x * SCAN_CHUNK;
        int v[4];
        int tsum = 0;
        #pragma unroll
        for (int j = 0; j < 4; j++) {
            int idx = base + t * 4 + j;
            v[j] = (idx < NN) ? g_degi[idx] : 0;
            tsum += v[j];
        }
        sdata[t] = tsum;
        __syncthreads();
        for (int off = 1; off < 256; off <<= 1) {
            int tmp = (t >= off) ? sdata[t - off] : 0;
            __syncthreads();
            sdata[t] += tmp;
            __syncthreads();
        }
        int run = sdata[t] - tsum + boff;
        #pragma unroll
        for (int j = 0; j < 4; j++) {
            int idx = base + t * 4 + j;
            if (idx < NN) {
                g_rowptr[idx] = run;
                g_cursor[idx] = run;
                run += v[j];
            }
        }
    }

    // convert: each item = 8 e4m3 bytes (uint2). NN*16 items.
    int total = NN * 16;
    for (int i = blockIdx.x * blockDim.x + threadIdx.x; i < total;
         i += gridDim.x * blockDim.x) {
        int node = i >> 4;
        int sub  = i & 15;
        int eo   = sub * 8;       // element (=byte) offset within 128-row
        float sc = 16.0f * rsqrtf(fmaxf((float)g_dego[node], 1.0f));
        const float* s = (eo < 64) ? (ei + (size_t)node * D + eo)
                                   : (ep + (size_t)node * D + (eo - 64));
        float4 v0 = *reinterpret_cast<const float4*>(s);
        float4 v1 = *reinterpret_cast<const float4*>(s + 4);
        unsigned a0 = __nv_cvt_float2_to_fp8x2(make_float2(v0.x * sc, v0.y * sc), __NV_SATFINITE, __NV_E4M3);
        unsigned a1 = __nv_cvt_float2_to_fp8x2(make_float2(v0.z * sc, v0.w * sc), __NV_SATFINITE, __NV_E4M3);
        unsigned a2 = __nv_cvt_float2_to_fp8x2(make_float2(v1.x * sc, v1.y * sc), __NV_SATFINITE, __NV_E4M3);
        unsigned a3 = __nv_cvt_float2_to_fp8x2(make_float2(v1.z * sc, v1.w * sc), __NV_SATFINITE, __NV_E4M3);
        uint2 ow;
        ow.x = (a0 & 0xFFFFu) | (a1 << 16);
        ow.y = (a2 & 0xFFFFu) | (a3 << 16);
        *reinterpret_cast<uint2*>(g_E + (size_t)node * ROWB + eo) = ow;
    }
}

// Edge placement (src index only).
__global__ void k_place(const int* __restrict__ es, const int* __restrict__ ed) {
    int i = blockIdx.x * blockDim.x + threadIdx.x;
    if (i >= E_EDGES) return;
    int s = es[i];
    int d = ed[i];
    int pos = atomicAdd(&g_cursor[d], 1);
    g_csr[pos] = s;
}

// CSR gather: 16 lanes per node, 2 nodes per warp. Row = 128B e4m3 (one L2 line).
// Each lane loads uint2 (8 e4m3), converts, accumulates in fp16.
// Per-node factor rdo*rdi applied in fp32 at store. prune != 0: skip unneeded nodes.
__global__ void __launch_bounds__(256)
k_gather(const unsigned char* __restrict__ src, unsigned char* __restrict__ dst, int prune) {
    unsigned t = blockIdx.x * blockDim.x + threadIdx.x;
    unsigned warp = t >> 5;
    unsigned lane = t & 31u;
    unsigned grp  = lane >> 4;      // 0 or 1
    unsigned gl   = lane & 15u;     // lane within group
    unsigned node = warp * 2 + grp;
    if (node >= (unsigned)NN) return;
    if (prune && !g_need[node]) return;

    const unsigned gmask = 0xFFFFu << (grp * 16);
    const int gbase = grp * 16;
    const int c = gl * 8;           // byte offset within 128B row

    int start = g_rowptr[node];
    int cnt   = g_degi[node];

    __half2 zz = __floats2half2_rn(0.f, 0.f);
    __half2 acch[4] = { zz, zz, zz, zz };

    for (int k0 = 0; k0 < cnt; k0 += 16) {
        int kk = k0 + (int)gl;
        int sidx = 0;
        if (kk < cnt) sidx = g_csr[start + kk];
        int lim = min(16, cnt - k0);
        int j = 0;
        for (; j + 4 <= lim; j += 4) {
            int s0 = __shfl_sync(gmask, sidx, gbase + j + 0);
            int s1 = __shfl_sync(gmask, sidx, gbase + j + 1);
            int s2 = __shfl_sync(gmask, sidx, gbase + j + 2);
            int s3 = __shfl_sync(gmask, sidx, gbase + j + 3);
            uint2 r0 = __ldg(reinterpret_cast<const uint2*>(src + (size_t)s0 * ROWB + c));
            uint2 r1 = __ldg(reinterpret_cast<const uint2*>(src + (size_t)s1 * ROWB + c));
            uint2 r2 = __ldg(reinterpret_cast<const uint2*>(src + (size_t)s2 * ROWB + c));
            uint2 r3 = __ldg(reinterpret_cast<const uint2*>(src + (size_t)s3 * ROWB + c));
            acc_fp8_8(acch, r0);
            acc_fp8_8(acch, r1);
            acc_fp8_8(acch, r2);
            acc_fp8_8(acch, r3);
        }
        for (; j < lim; j++) {
            int sj = __shfl_sync(gmask, sidx, gbase + j);
            uint2 rv = __ldg(reinterpret_cast<const uint2*>(src + (size_t)sj * ROWB + c));
            acc_fp8_8(acch, rv);
        }
    }

    float rs = rsqrtf(fmaxf((float)g_dego[node], 1.0f))
             * rsqrtf(fmaxf((float)g_degi[node], 1.0f));
    unsigned o[4];
    #pragma unroll
    for (int i2 = 0; i2 < 4; i2++) {
        float2 f = __half22float2(acch[i2]);
        o[i2] = __nv_cvt_float2_to_fp8x2(make_float2(f.x * rs, f.y * rs),
                                         __NV_SATFINITE, __NV_E4M3);
    }
    uint2 outw;
    outw.x = (o[0] & 0xFFFFu) | (o[1] << 16);
    outw.y = (o[2] & 0xFFFFu) | (o[3] << 16);
    *reinterpret_cast<uint2*>(dst + (size_t)node * ROWB + c) = outw;
}

// One warp per triple. f-row (x4) = e0 + (sqrt(dego)/16) * (S_A + S_B + S_C).
// Dots scale by 1/16 (4-layer mean squared).
__global__ void __launch_bounds__(256)
k_score(const float* __restrict__ ei, const float* __restrict__ ep,
        const float* __restrict__ q, const float* __restrict__ bq,
        const int* __restrict__ user, const int* __restrict__ itp,
        const int* __restrict__ itn, const void* __restrict__ mask) {
    int t = blockIdx.x * blockDim.x + threadIdx.x;
    int w = t >> 5;
    int lane = t & 31;
    int wib = (threadIdx.x >> 5);
    __shared__ float sred[8][4];

    float s0 = 0.f, s1 = 0.f, s2 = 0.f, s3 = 0.f;
    if (w < BATCH) {
        int u  = user[w];
        int p  = itp[w];
        int n  = itn[w];

        auto rowsum = [&](const float* e, int node, int pop) -> float2 {
            size_t re = (size_t)node * D;
            size_t rh = (size_t)node * ROWB + pop * 64 + lane * 2;
            float sq = sqrtf(fmaxf((float)g_dego[node], 1.0f)) * 0.0625f;
            float2 x = reinterpret_cast<const float2*>(e + re)[lane];
            float2 fa = fp8x2_to_float2(*reinterpret_cast<const unsigned short*>(g_A + rh));
            float2 fb = fp8x2_to_float2(*reinterpret_cast<const unsigned short*>(g_B + rh));
            float2 fc = fp8x2_to_float2(*reinterpret_cast<const unsigned short*>(g_C + rh));
            return make_float2(x.x + sq * (fa.x + fb.x + fc.x),
                               x.y + sq * (fa.y + fb.y + fc.y));
        };

        int np = p + N_USER;
        int nn = n + N_USER;
        float2 a  = rowsum(ei, u, 0);
        float2 bb = rowsum(ep, u, 1);
        float2 cp = rowsum(ei, np, 0);
        float2 dp = rowsum(ep, np, 1);
        float2 cn = rowsum(ei, nn, 0);
        float2 dn = rowsum(ep, nn, 1);

        float pint = a.x * cp.x + a.y * cp.y;
        float nint = a.x * cn.x + a.y * cn.y;
        float ppop = bb.x * dp.x + bb.y * dp.y;
        float npop = bb.x * dn.x + bb.y * dn.y;

        #pragma unroll
        for (int o = 16; o > 0; o >>= 1) {
            pint += __shfl_xor_sync(0xffffffffu, pint, o);
            nint += __shfl_xor_sync(0xffffffffu, nint, o);
            ppop += __shfl_xor_sync(0xffffffffu, ppop, o);
            npop += __shfl_xor_sync(0xffffffffu, npop, o);
        }

        if (lane == 0) {
            const float inv16 = 0.0625f;
            pint *= inv16; nint *= inv16; ppop *= inv16; npop *= inv16;

            bool m;
            if (g_mask_is_u8)
                m = ((const unsigned char*)mask)[w] != 0;
            else
                m = ((const int*)mask)[w] != 0;
            float mf = m ? 1.0f : 0.0f;
            float nmf = 1.0f - mf;

            s0 = mf  * logsig_f(pint - nint);
            s1 = mf  * logsig_f(npop - ppop);
            s2 = nmf * logsig_f(ppop - npop);

            float popp = softplus_f(q[p]) + softplus_f(bq[p]);
            float popn = softplus_f(q[n]) + softplus_f(bq[n]);
            float ptot = pint + ppop;
            float ntot = nint + npop;
            s3 = logsig_f(tanhf(popp) * ptot - tanhf(popn) * ntot);
        }
    }
    if (lane == 0) {
        sred[wib][0] = s0; sred[wib][1] = s1; sred[wib][2] = s2; sred[wib][3] = s3;
    }
    __syncthreads();
    if (threadIdx.x < 4) {
        float tsum = 0.f;
        #pragma unroll
        for (int k = 0; k < 8; k++) tsum += sred[k][threadIdx.x];
        atomicAdd(&g_sums[threadIdx.x], (double)tsum);
    }
}

__global__ void k_final(float* __restrict__ out) {
    double invB = 1.0 / (double)BATCH;
    double s0 = g_sums[0], s1 = g_sums[1], s2 = g_sums[2], s3 = g_sums[3];
    double loss_int  = -s0 * invB;
    double loss_pop  = (-s1 + s2) * invB;
    double loss_tide = -s3 * invB;
    out[0] = (float)(0.1 * loss_int + 0.1 * loss_pop + 0.2 * loss_tide);
}

// ---------------- launch ------------------------------------------------------
extern "C" void kernel_launch(void* const* d_in, const int* in_sizes, int n_in,
                              void* d_out, int out_size) {
    const float* emb_int = (const float*)d_in[0];
    const float* emb_pop = (const float*)d_in[1];
    const float* q       = (const float*)d_in[2];
    const float* bq      = (const float*)d_in[3];
    const int*   user    = (const int*)d_in[4];
    const int*   itp     = (const int*)d_in[5];
    const int*   itn     = (const int*)d_in[6];
    const void*  mask    = d_in[7];
    const int*   es      = (const int*)d_in[8];
    const int*   ed      = (const int*)d_in[9];
    float* out = (float*)d_out;

    const int TB = 256;
    int gridE  = (E_EDGES + TB - 1) / TB;
    int gridN  = (NN + TB - 1) / TB;
    int gridC  = (NN * 16 + TB - 1) / TB;   // convert items (also covers scan blocks)
    long long warpsG = (NN + 1) / 2;
    int gridG  = (int)((warpsG * 32 + TB - 1) / TB);
    int gridS  = (BATCH * 32 + TB - 1) / TB;

    unsigned char *E, *A, *B, *C;
    cudaGetSymbolAddress((void**)&E, g_E);
    cudaGetSymbolAddress((void**)&A, g_A);
    cudaGetSymbolAddress((void**)&B, g_B);
    cudaGetSymbolAddress((void**)&C, g_C);

    k_init<<<gridN, TB>>>();
    k_degree<<<gridE, TB>>>(es, ed, (const unsigned char*)mask, user, itp, itn);
    k_scan_a<<<NB_SCAN, 256>>>();
    k_scan_bc_convert<<<gridC, 256>>>(emb_int, emb_pop);
    k_place<<<gridE, TB>>>(es, ed);

    k_gather<<<gridG, TB>>>(E, A, 0);   // layer 1  (6th launch -> ncu capture)
    k_gather<<<gridG, TB>>>(A, B, 0);   // layer 2
    k_gather<<<gridG, TB>>>(B, C, 1);   // layer 3 (pruned)

    k_score<<<gridS, TB>>>(emb_int, emb_pop, q, bq, user, itp, itn, mask);
    k_final<<<1, 1>>>(out);
}

// round 8
// speedup vs baseline: 6.3918x; 1.1580x over previous
#include <cuda_runtime.h>
#include <cuda_fp16.h>
#include <cuda_fp8.h>
#include <math.h>

// Problem constants (fixed-shape problem)
static constexpr int N_USER  = 100000;
static constexpr int N_ITEM  = 50000;
static constexpr int NN      = N_USER + N_ITEM;   // 150000
static constexpr int D       = 64;
static constexpr int ROWB    = 128;               // row bytes: 64 int + 64 pop e4m3
static constexpr int E_EDGES = 2000000;
static constexpr int BATCH   = 8192;

static constexpr int SCAN_CHUNK = 1024;
static constexpr int NB_SCAN = (NN + SCAN_CHUNK - 1) / SCAN_CHUNK;  // 147

// All fp8 buffers store 16x the true value (descaled in k_score).
// ---------------- device scratch (static globals, no allocation) -------------
__device__ int    g_dego[NN];
__device__ int    g_degi[NN];
__device__ int    g_rowptr[NN];
__device__ int    g_cursor[NN];
__device__ int    g_bsum[NB_SCAN];
__device__ int    g_dhist[256];        // degree histogram (clamped)
__device__ int    g_dcur[256];         // bucket cursors (exclusive prefix)
__device__ int    g_order[NN];         // nodes sorted by in-degree
__device__ int    g_csr[E_EDGES];      // src node only (norm factored out)
__device__ unsigned char g_need[NN];   // layer-3 pruning flags
__device__ unsigned char g_E[(size_t)NN * ROWB];   // 16*rdo*emb  (e4m3)
__device__ unsigned char g_A[(size_t)NN * ROWB];
__device__ unsigned char g_B[(size_t)NN * ROWB];
__device__ unsigned char g_C[(size_t)NN * ROWB];
__device__ double g_sums[4];
__device__ int    g_mask_is_u8;

// ---------------- helpers ----------------------------------------------------
__device__ __forceinline__ float softplus_f(float x) {
    return fmaxf(x, 0.0f) + log1pf(expf(-fabsf(x)));
}
__device__ __forceinline__ float logsig_f(float x) {
    return fminf(x, 0.0f) - log1pf(expf(-fabsf(x)));
}
// acch[8] (half2) += 16 e4m3 values packed in uint4
__device__ __forceinline__ void acc_fp8_16(__half2* acch, uint4 raw) {
    #pragma unroll
    for (int k = 0; k < 4; k++) {
        unsigned w = (&raw.x)[k];
        __half2_raw h0 = __nv_cvt_fp8x2_to_halfraw2((__nv_fp8x2_storage_t)(w & 0xFFFFu), __NV_E4M3);
        __half2_raw h1 = __nv_cvt_fp8x2_to_halfraw2((__nv_fp8x2_storage_t)(w >> 16), __NV_E4M3);
        acch[2*k]   = __hadd2(acch[2*k],   *reinterpret_cast<__half2*>(&h0));
        acch[2*k+1] = __hadd2(acch[2*k+1], *reinterpret_cast<__half2*>(&h1));
    }
}
__device__ __forceinline__ float2 fp8x2_to_float2(unsigned short v) {
    __half2_raw h = __nv_cvt_fp8x2_to_halfraw2((__nv_fp8x2_storage_t)v, __NV_E4M3);
    return __half22float2(*reinterpret_cast<__half2*>(&h));
}

// ---------------- kernels ----------------------------------------------------
// Zero degrees / flags / sums / histogram.
__global__ void k_init() {
    int i = blockIdx.x * blockDim.x + threadIdx.x;
    if (i < NN) { g_dego[i] = 0; g_degi[i] = 0; g_need[i] = 0; }
    if (i < 256) g_dhist[i] = 0;
    if (i < 4)  g_sums[i] = 0.0;
    if (i == 0) g_mask_is_u8 = 0;
}

// Degree counting + mask-layout detect + layer-3 need flags.
__global__ void k_degree(const int* __restrict__ es, const int* __restrict__ ed,
                         const unsigned char* __restrict__ m,
                         const int* __restrict__ user, const int* __restrict__ itp,
                         const int* __restrict__ itn) {
    int i = blockIdx.x * blockDim.x + threadIdx.x;
    if (i < BATCH) {
        if ((i & 3) && m[i]) atomicOr(&g_mask_is_u8, 1);
        g_need[user[i]] = 1;
        g_need[itp[i] + N_USER] = 1;
        g_need[itn[i] + N_USER] = 1;
    }
    if (i >= E_EDGES) return;
    atomicAdd(&g_dego[es[i]], 1);
    atomicAdd(&g_degi[ed[i]], 1);
}

// Per-chunk sums of g_degi + block-aggregated degree histogram.
__global__ void k_scan_a() {
    __shared__ int sdata[256];
    __shared__ int shist[256];
    int base = blockIdx.x * SCAN_CHUNK;
    int t = threadIdx.x;
    shist[t] = 0;
    __syncthreads();
    int s = 0;
    #pragma unroll
    for (int j = 0; j < 4; j++) {
        int idx = base + t * 4 + j;
        if (idx < NN) {
            int d = g_degi[idx];
            s += d;
            atomicAdd(&shist[min(d, 255)], 1);
        }
    }
    sdata[t] = s;
    __syncthreads();
    for (int off = 128; off > 0; off >>= 1) {
        if (t < off) sdata[t] += sdata[t + off];
        __syncthreads();
    }
    if (t == 0) g_bsum[blockIdx.x] = sdata[0];
    if (shist[t]) atomicAdd(&g_dhist[t], shist[t]);
}

// Fused: blocks [0, NB_SCAN) build rowptr/cursor; block NB_SCAN scans the
// degree histogram; ALL blocks run grid-stride fp32 -> e4m3 (x16*rdo) convert.
__global__ void k_scan_bc_convert(const float* __restrict__ ei, const float* __restrict__ ep) {
    __shared__ int sb[256];
    __shared__ int sdata[256];
    int t = threadIdx.x;

    if (blockIdx.x < NB_SCAN) {
        sb[t] = (t < NB_SCAN) ? g_bsum[t] : 0;
        __syncthreads();
        for (int off = 1; off < 256; off <<= 1) {
            int tmp = (t >= off) ? sb[t - off] : 0;
            __syncthreads();
            sb[t] += tmp;
            __syncthreads();
        }
        int boff = (blockIdx.x == 0) ? 0 : sb[blockIdx.x - 1];

        int base = blockIdx.x * SCAN_CHUNK;
        int v[4];
        int tsum = 0;
        #pragma unroll
        for (int j = 0; j < 4; j++) {
            int idx = base + t * 4 + j;
            v[j] = (idx < NN) ? g_degi[idx] : 0;
            tsum += v[j];
        }
        sdata[t] = tsum;
        __syncthreads();
        for (int off = 1; off < 256; off <<= 1) {
            int tmp = (t >= off) ? sdata[t - off] : 0;
            __syncthreads();
            sdata[t] += tmp;
            __syncthreads();
        }
        int run = sdata[t] - tsum + boff;
        #pragma unroll
        for (int j = 0; j < 4; j++) {
            int idx = base + t * 4 + j;
            if (idx < NN) {
                g_rowptr[idx] = run;
                g_cursor[idx] = run;
                run += v[j];
            }
        }
    } else if (blockIdx.x == NB_SCAN) {
        // exclusive scan of degree histogram -> bucket cursors
        int v = g_dhist[t];
        sb[t] = v;
        __syncthreads();
        for (int off = 1; off < 256; off <<= 1) {
            int tmp = (t >= off) ? sb[t - off] : 0;
            __syncthreads();
            sb[t] += tmp;
            __syncthreads();
        }
        g_dcur[t] = sb[t] - v;
    }

    // convert: each item = 8 e4m3 bytes (uint2). NN*16 items.
    int total = NN * 16;
    for (int i = blockIdx.x * blockDim.x + threadIdx.x; i < total;
         i += gridDim.x * blockDim.x) {
        int node = i >> 4;
        int sub  = i & 15;
        int eo   = sub * 8;       // element (=byte) offset within 128-row
        float sc = 16.0f * rsqrtf(fmaxf((float)g_dego[node], 1.0f));
        const float* s = (eo < 64) ? (ei + (size_t)node * D + eo)
                                   : (ep + (size_t)node * D + (eo - 64));
        float4 v0 = *reinterpret_cast<const float4*>(s);
        float4 v1 = *reinterpret_cast<const float4*>(s + 4);
        unsigned a0 = __nv_cvt_float2_to_fp8x2(make_float2(v0.x * sc, v0.y * sc), __NV_SATFINITE, __NV_E4M3);
        unsigned a1 = __nv_cvt_float2_to_fp8x2(make_float2(v0.z * sc, v0.w * sc), __NV_SATFINITE, __NV_E4M3);
        unsigned a2 = __nv_cvt_float2_to_fp8x2(make_float2(v1.x * sc, v1.y * sc), __NV_SATFINITE, __NV_E4M3);
        unsigned a3 = __nv_cvt_float2_to_fp8x2(make_float2(v1.z * sc, v1.w * sc), __NV_SATFINITE, __NV_E4M3);
        uint2 ow;
        ow.x = (a0 & 0xFFFFu) | (a1 << 16);
        ow.y = (a2 & 0xFFFFu) | (a3 << 16);
        *reinterpret_cast<uint2*>(g_E + (size_t)node * ROWB + eo) = ow;
    }
}

// Edge placement + degree-sorted node order scatter.
__global__ void k_place(const int* __restrict__ es, const int* __restrict__ ed) {
    int i = blockIdx.x * blockDim.x + threadIdx.x;
    if (i < E_EDGES) {
        int s = es[i];
        int d = ed[i];
        int pos = atomicAdd(&g_cursor[d], 1);
        g_csr[pos] = s;
    }
    // node-order scatter (grid covers E_EDGES > NN)
    if (i < NN) {
        int b = min(g_degi[i], 255);
        int pos = atomicAdd(&g_dcur[b], 1);
        g_order[pos] = i;
    }
}

// CSR gather: 8 lanes per node, 4 nodes per warp, degree-sorted node order.
// Row = 128B e4m3 (one line); each lane loads uint4 (16 fp8 = 16B).
// CSR indices loaded uniformly per group (broadcast), no shuffles.
// Per-node factor rdo*rdi applied in fp32 at store. prune != 0: skip unneeded.
__global__ void __launch_bounds__(256)
k_gather(const unsigned char* __restrict__ src, unsigned char* __restrict__ dst, int prune) {
    unsigned t = blockIdx.x * blockDim.x + threadIdx.x;
    unsigned warp = t >> 5;
    unsigned lane = t & 31u;
    unsigned grp  = lane >> 3;      // 0..3
    unsigned gl   = lane & 7u;      // lane within group
    unsigned idx  = warp * 4 + grp;
    if (idx >= (unsigned)NN) return;
    int node = g_order[idx];
    if (prune && !g_need[node]) return;

    const int c = (int)gl * 16;     // byte offset within 128B row

    int start = g_rowptr[node];
    int cnt   = g_degi[node];

    __half2 zz = __floats2half2_rn(0.f, 0.f);
    __half2 acch[8] = { zz, zz, zz, zz, zz, zz, zz, zz };

    int j = 0;
    for (; j + 4 <= cnt; j += 4) {
        int s0 = __ldg(&g_csr[start + j + 0]);
        int s1 = __ldg(&g_csr[start + j + 1]);
        int s2 = __ldg(&g_csr[start + j + 2]);
        int s3 = __ldg(&g_csr[start + j + 3]);
        uint4 r0 = __ldg(reinterpret_cast<const uint4*>(src + (size_t)s0 * ROWB + c));
        uint4 r1 = __ldg(reinterpret_cast<const uint4*>(src + (size_t)s1 * ROWB + c));
        uint4 r2 = __ldg(reinterpret_cast<const uint4*>(src + (size_t)s2 * ROWB + c));
        uint4 r3 = __ldg(reinterpret_cast<const uint4*>(src + (size_t)s3 * ROWB + c));
        acc_fp8_16(acch, r0);
        acc_fp8_16(acch, r1);
        acc_fp8_16(acch, r2);
        acc_fp8_16(acch, r3);
    }
    for (; j < cnt; j++) {
        int sj = __ldg(&g_csr[start + j]);
        uint4 rv = __ldg(reinterpret_cast<const uint4*>(src + (size_t)sj * ROWB + c));
        acc_fp8_16(acch, rv);
    }

    float rs = rsqrtf(fmaxf((float)g_dego[node], 1.0f))
             * rsqrtf(fmaxf((float)g_degi[node], 1.0f));
    uint4 outw;
    #pragma unroll
    for (int k = 0; k < 4; k++) {
        float2 f0 = __half22float2(acch[2*k]);
        float2 f1 = __half22float2(acch[2*k+1]);
        unsigned o0 = __nv_cvt_float2_to_fp8x2(make_float2(f0.x * rs, f0.y * rs),
                                               __NV_SATFINITE, __NV_E4M3);
        unsigned o1 = __nv_cvt_float2_to_fp8x2(make_float2(f1.x * rs, f1.y * rs),
                                               __NV_SATFINITE, __NV_E4M3);
        (&outw.x)[k] = (o0 & 0xFFFFu) | (o1 << 16);
    }
    *reinterpret_cast<uint4*>(dst + (size_t)node * ROWB + c) = outw;
}

// One warp per triple. f-row (x4) = e0 + (sqrt(dego)/16) * (S_A + S_B + S_C).
// Dots scale by 1/16 (4-layer mean squared).
__global__ void __launch_bounds__(256)
k_score(const float* __restrict__ ei, const float* __restrict__ ep,
        const float* __restrict__ q, const float* __restrict__ bq,
        const int* __restrict__ user, const int* __restrict__ itp,
        const int* __restrict__ itn, const void* __restrict__ mask) {
    int t = blockIdx.x * blockDim.x + threadIdx.x;
    int w = t >> 5;
    int lane = t & 31;
    int wib = (threadIdx.x >> 5);
    __shared__ float sred[8][4];

    float s0 = 0.f, s1 = 0.f, s2 = 0.f, s3 = 0.f;
    if (w < BATCH) {
        int u  = user[w];
        int p  = itp[w];
        int n  = itn[w];

        auto rowsum = [&](const float* e, int node, int pop) -> float2 {
            size_t re = (size_t)node * D;
            size_t rh = (size_t)node * ROWB + pop * 64 + lane * 2;
            float sq = sqrtf(fmaxf((float)g_dego[node], 1.0f)) * 0.0625f;
            float2 x = reinterpret_cast<const float2*>(e + re)[lane];
            float2 fa = fp8x2_to_float2(*reinterpret_cast<const unsigned short*>(g_A + rh));
            float2 fb = fp8x2_to_float2(*reinterpret_cast<const unsigned short*>(g_B + rh));
            float2 fc = fp8x2_to_float2(*reinterpret_cast<const unsigned short*>(g_C + rh));
            return make_float2(x.x + sq * (fa.x + fb.x + fc.x),
                               x.y + sq * (fa.y + fb.y + fc.y));
        };

        int np = p + N_USER;
        int nn = n + N_USER;
        float2 a  = rowsum(ei, u, 0);
        float2 bb = rowsum(ep, u, 1);
        float2 cp = rowsum(ei, np, 0);
        float2 dp = rowsum(ep, np, 1);
        float2 cn = rowsum(ei, nn, 0);
        float2 dn = rowsum(ep, nn, 1);

        float pint = a.x * cp.x + a.y * cp.y;
        float nint = a.x * cn.x + a.y * cn.y;
        float ppop = bb.x * dp.x + bb.y * dp.y;
        float npop = bb.x * dn.x + bb.y * dn.y;

        #pragma unroll
        for (int o = 16; o > 0; o >>= 1) {
            pint += __shfl_xor_sync(0xffffffffu, pint, o);
            nint += __shfl_xor_sync(0xffffffffu, nint, o);
            ppop += __shfl_xor_sync(0xffffffffu, ppop, o);
            npop += __shfl_xor_sync(0xffffffffu, npop, o);
        }

        if (lane == 0) {
            const float inv16 = 0.0625f;
            pint *= inv16; nint *= inv16; ppop *= inv16; npop *= inv16;

            bool m;
            if (g_mask_is_u8)
                m = ((const unsigned char*)mask)[w] != 0;
            else
                m = ((const int*)mask)[w] != 0;
            float mf = m ? 1.0f : 0.0f;
            float nmf = 1.0f - mf;

            s0 = mf  * logsig_f(pint - nint);
            s1 = mf  * logsig_f(npop - ppop);
            s2 = nmf * logsig_f(ppop - npop);

            float popp = softplus_f(q[p]) + softplus_f(bq[p]);
            float popn = softplus_f(q[n]) + softplus_f(bq[n]);
            float ptot = pint + ppop;
            float ntot = nint + npop;
            s3 = logsig_f(tanhf(popp) * ptot - tanhf(popn) * ntot);
        }
    }
    if (lane == 0) {
        sred[wib][0] = s0; sred[wib][1] = s1; sred[wib][2] = s2; sred[wib][3] = s3;
    }
    __syncthreads();
    if (threadIdx.x < 4) {
        float tsum = 0.f;
        #pragma unroll
        for (int k = 0; k < 8; k++) tsum += sred[k][threadIdx.x];
        atomicAdd(&g_sums[threadIdx.x], (double)tsum);
    }
}

__global__ void k_final(float* __restrict__ out) {
    double invB = 1.0 / (double)BATCH;
    double s0 = g_sums[0], s1 = g_sums[1], s2 = g_sums[2], s3 = g_sums[3];
    double loss_int  = -s0 * invB;
    double loss_pop  = (-s1 + s2) * invB;
    double loss_tide = -s3 * invB;
    out[0] = (float)(0.1 * loss_int + 0.1 * loss_pop + 0.2 * loss_tide);
}

// ---------------- launch ------------------------------------------------------
extern "C" void kernel_launch(void* const* d_in, const int* in_sizes, int n_in,
                              void* d_out, int out_size) {
    const float* emb_int = (const float*)d_in[0];
    const float* emb_pop = (const float*)d_in[1];
    const float* q       = (const float*)d_in[2];
    const float* bq      = (const float*)d_in[3];
    const int*   user    = (const int*)d_in[4];
    const int*   itp     = (const int*)d_in[5];
    const int*   itn     = (const int*)d_in[6];
    const void*  mask    = d_in[7];
    const int*   es      = (const int*)d_in[8];
    const int*   ed      = (const int*)d_in[9];
    float* out = (float*)d_out;

    const int TB = 256;
    int gridE  = (E_EDGES + TB - 1) / TB;
    int gridN  = (NN + TB - 1) / TB;
    int gridC  = (NN * 16 + TB - 1) / TB;
    long long warpsG = (NN + 3) / 4;
    int gridG  = (int)((warpsG * 32 + TB - 1) / TB);
    int gridS  = (BATCH * 32 + TB - 1) / TB;

    unsigned char *E, *A, *B, *C;
    cudaGetSymbolAddress((void**)&E, g_E);
    cudaGetSymbolAddress((void**)&A, g_A);
    cudaGetSymbolAddress((void**)&B, g_B);
    cudaGetSymbolAddress((void**)&C, g_C);

    k_init<<<gridN, TB>>>();
    k_degree<<<gridE, TB>>>(es, ed, (const unsigned char*)mask, user, itp, itn);
    k_scan_a<<<NB_SCAN, 256>>>();
    k_scan_bc_convert<<<gridC, 256>>>(emb_int, emb_pop);
    k_place<<<gridE, TB>>>(es, ed);

    k_gather<<<gridG, TB>>>(E, A, 0);   // layer 1
    k_gather<<<gridG, TB>>>(A, B, 0);   // layer 2
    k_gather<<<gridG, TB>>>(B, C, 1);   // layer 3 (pruned)

    k_score<<<gridS, TB>>>(emb_int, emb_pop, q, bq, user, itp, itn, mask);
    k_final<<<1, 1>>>(out);
}